// round 4
// baseline (speedup 1.0000x reference)
#include <cuda_runtime.h>
#include <math.h>

#define B_    32
#define T_    1024
#define H_    1024
#define FH_   4096
#define DIN_  256
#define DOUT_ 512
#define BT_   (B_*T_)
#define NBLK_ 128           // persistent-kernel grid (1 block per SM guaranteed by smem)

// -------- scratch (static device globals; no allocation anywhere) ----------
__device__ float g_XZ[(size_t)BT_*FH_];   // 512 MB, reused for layer1 and layer2 xz
__device__ float g_H1[(size_t)BT_*H_];    // 128 MB
__device__ float g_H2[(size_t)BT_*H_];    // 128 MB
__device__ float g_hbuf[2][B_*H_];        // double-buffered hidden state

// grid barrier state (persists across replays; generation-relative, so safe)
__device__ unsigned          g_bar_count = 0;
__device__ volatile unsigned g_bar_gen   = 0;

__device__ __forceinline__ void grid_sync(unsigned* gen_local)
{
    __syncthreads();
    if (threadIdx.x == 0) {
        unsigned my = *gen_local;
        __threadfence();
        unsigned arr = atomicAdd(&g_bar_count, 1u);
        if (arr == NBLK_ - 1) {
            g_bar_count = 0;
            __threadfence();
            g_bar_gen = my + 1;
        } else {
            while (g_bar_gen == my) { }
        }
        *gen_local = my + 1;
    }
    __syncthreads();
}

// ---------------------------------------------------------------------------
// fp32 GEMM + bias (+ optional softplus). C[M,N] = A[M,K]@B[K,N] + bias.
// 128x64 tile, 256 threads, 8x4 per thread, BK=16. M%128==0, N%64==0, K%16==0.
// ---------------------------------------------------------------------------
template<int EPI>
__global__ void gemm_bias(const float* __restrict__ A, const float* __restrict__ Bm,
                          const float* __restrict__ bias, float* __restrict__ C,
                          int M, int N, int K, int ldc)
{
    __shared__ float As[16][132];   // A transposed, 16B-aligned rows
    __shared__ float Bs[16][64];

    const int tid = threadIdx.x;
    const int tx  = tid & 15;       // n-group (4 cols each)
    const int ty  = tid >> 4;       // m-group (8 rows each)
    const int bm  = blockIdx.y * 128;
    const int bn  = blockIdx.x * 64;

    float acc[8][4] = {};

    for (int k0 = 0; k0 < K; k0 += 16) {
        // A tile: 128 rows x 16 cols, coalesced on K, stored transposed
        #pragma unroll
        for (int p = 0; p < 8; p++) {
            int r = (tid >> 4) + p * 16;
            int c = tid & 15;
            As[c][r] = A[(size_t)(bm + r) * K + k0 + c];
        }
        // B tile: 16 rows x 64 cols, float4 coalesced
        {
            int r  = tid >> 4;
            int c4 = tid & 15;
            *(float4*)&Bs[r][c4 * 4] =
                *(const float4*)&Bm[(size_t)(k0 + r) * N + bn + c4 * 4];
        }
        __syncthreads();

        #pragma unroll
        for (int k = 0; k < 16; k++) {
            float4 a0 = *(const float4*)&As[k][ty * 8];
            float4 a1 = *(const float4*)&As[k][ty * 8 + 4];
            float4 b  = *(const float4*)&Bs[k][tx * 4];
            float av[8] = {a0.x, a0.y, a0.z, a0.w, a1.x, a1.y, a1.z, a1.w};
            float bv[4] = {b.x, b.y, b.z, b.w};
            #pragma unroll
            for (int i = 0; i < 8; i++)
                #pragma unroll
                for (int j = 0; j < 4; j++)
                    acc[i][j] += av[i] * bv[j];
        }
        __syncthreads();
    }

    #pragma unroll
    for (int i = 0; i < 8; i++) {
        int row = bm + ty * 8 + i;
        #pragma unroll
        for (int j = 0; j < 4; j++) {
            int col = bn + tx * 4 + j;
            float v = acc[i][j] + bias[col];
            if (EPI == 1) v = (v > 20.f) ? v : log1pf(expf(v));  // softplus
            C[(size_t)row * ldc + col] = v;
        }
    }
}

// ---------------------------------------------------------------------------
// Persistent LSTM layer: the whole T=1024 recurrence in ONE kernel.
// 128 blocks x 256 threads. Block bid owns 8 hidden units u0..u0+7 (all 4
// gate columns), so the c/h update is block-local; c lives in registers.
// Block's Wh slice (1024 k x 8 u x 4 gates = 128KB) loaded into smem ONCE.
// h double-buffers through global (L2) with __ldcg readers; one grid barrier
// per timestep orders writer->reader.
// ---------------------------------------------------------------------------
__global__ void lstm_layer_persist(const float* __restrict__ Wh,   // [H, 4H]
                                   const float* __restrict__ XZ,   // [B*T, 4H] (bias folded)
                                   float* __restrict__ Hout)       // [B*T, H]
{
    extern __shared__ float smem[];
    float4* w_s = (float4*)smem;                 // [1024][8] float4 = 128KB
    float*  h_s = smem + H_ * 8 * 4;             // [32][64] = 8KB

    const int tid = threadIdx.x;
    const int ui  = tid & 7;
    const int b   = tid >> 3;
    const int u0  = blockIdx.x * 8;
    const int u   = u0 + ui;

    // --- one-time: load Wh slice, gate-interleaved: w_s[k][j] = {Wi,Wf,Wg,Wo} for unit u0+j
    for (int lin = tid; lin < H_ * 8; lin += 256) {
        int k   = lin >> 3;
        int rem = lin & 7;
        int g   = rem >> 1;
        int hf  = rem & 1;
        float4 wv = *(const float4*)&Wh[(size_t)k * FH_ + g * H_ + u0 + hf * 4];
        float* base = (float*)&w_s[(size_t)k * 8];
        base[(hf * 4 + 0) * 4 + g] = wv.x;
        base[(hf * 4 + 1) * 4 + g] = wv.y;
        base[(hf * 4 + 2) * 4 + g] = wv.z;
        base[(hf * 4 + 3) * 4 + g] = wv.w;
    }

    // --- init state: h0 = 0 (each thread owns one (b,u)), c in register
    const int sidx = b * H_ + u;
    g_hbuf[0][sidx] = 0.f;
    float c_reg = 0.f;

    unsigned gen_local;
    if (tid == 0) gen_local = g_bar_gen;
    __threadfence();
    grid_sync(&gen_local);

    for (int t = 0; t < T_; t++) {
        const float* hp = g_hbuf[t & 1];
        float*       hn = g_hbuf[(t + 1) & 1];

        // prefetch the xz gate inputs for this (b,u,t) early
        const size_t row = (size_t)b * T_ + t;
        const float* xz  = XZ + row * FH_;
        float xi = __ldg(&xz[u]);
        float xf = __ldg(&xz[H_ + u]);
        float xg = __ldg(&xz[2 * H_ + u]);
        float xo = __ldg(&xz[3 * H_ + u]);

        float ai = 0.f, af = 0.f, ag = 0.f, ao = 0.f;

        for (int k0 = 0; k0 < H_; k0 += 64) {
            // stage h chunk (32 b x 64 k) from L2, bypassing L1 (cross-SM data)
            {
                const float4* hp4 = (const float4*)hp;
                float4*       hs4 = (float4*)h_s;
                #pragma unroll
                for (int i = 0; i < 2; i++) {
                    int lin = tid + i * 256;
                    int bl = lin >> 4, kq = lin & 15;
                    hs4[lin] = __ldcg(&hp4[bl * (H_ / 4) + (k0 >> 2) + kq]);
                }
            }
            __syncthreads();

            const float4* wrow = w_s + (size_t)k0 * 8 + ui;
            #pragma unroll
            for (int k4 = 0; k4 < 16; k4++) {
                float4 h4 = *(const float4*)&h_s[b * 64 + k4 * 4];
                float hv4[4] = {h4.x, h4.y, h4.z, h4.w};
                #pragma unroll
                for (int q = 0; q < 4; q++) {
                    float4 w = wrow[(k4 * 4 + q) * 8];
                    float hv = hv4[q];
                    ai += hv * w.x;
                    af += hv * w.y;
                    ag += hv * w.z;
                    ao += hv * w.w;
                }
            }
            __syncthreads();
        }

        float zi = xi + ai;
        float zf = xf + af;
        float zg = xg + ag;
        float zo = xo + ao;

        float iv = 1.f / (1.f + expf(-zi));
        float fv = 1.f / (1.f + expf(-zf));
        float gv = tanhf(zg);
        float ov = 1.f / (1.f + expf(-zo));

        c_reg = fv * c_reg + iv * gv;
        float hv = ov * tanhf(c_reg);

        hn[sidx] = hv;
        Hout[row * H_ + u] = hv;

        __threadfence();
        grid_sync(&gen_local);
    }
}

// ---------------------------------------------------------------------------
extern "C" void kernel_launch(void* const* d_in, const int* in_sizes, int n_in,
                              void* d_out, int out_size)
{
    const float* obs = (const float*)d_in[0];
    const float* W1x = (const float*)d_in[1];
    const float* W1h = (const float*)d_in[2];
    const float* b1  = (const float*)d_in[3];
    const float* W2x = (const float*)d_in[4];
    const float* W2h = (const float*)d_in[5];
    const float* b2  = (const float*)d_in[6];
    const float* Wm  = (const float*)d_in[7];
    const float* bm  = (const float*)d_in[8];
    const float* Wc  = (const float*)d_in[9];
    const float* bc  = (const float*)d_in[10];

    float *XZ, *H1, *H2;
    cudaGetSymbolAddress((void**)&XZ, g_XZ);
    cudaGetSymbolAddress((void**)&H1, g_H1);
    cudaGetSymbolAddress((void**)&H2, g_H2);

    float* out = (float*)d_out;
    size_t half = (size_t)out_size / 2;   // mean | cov

    const int DSMEM = H_ * 8 * 4 * (int)sizeof(float) + 32 * 64 * (int)sizeof(float); // 128KB + 8KB
    static int attr_done = 0;
    if (!attr_done) {
        cudaFuncSetAttribute(lstm_layer_persist,
                             cudaFuncAttributeMaxDynamicSharedMemorySize, DSMEM);
        attr_done = 1;
    }

    // XZ1 = obs @ W1x + b1
    gemm_bias<0><<<dim3(FH_ / 64, BT_ / 128), 256>>>(obs, W1x, b1, XZ, BT_, FH_, DIN_, FH_);

    // Layer 1 recurrence (one persistent kernel)
    lstm_layer_persist<<<NBLK_, 256, DSMEM>>>(W1h, XZ, H1);

    // XZ2 = H1 @ W2x + b2  (reuse XZ buffer)
    gemm_bias<0><<<dim3(FH_ / 64, BT_ / 128), 256>>>(H1, W2x, b2, XZ, BT_, FH_, H_, FH_);

    // Layer 2 recurrence
    lstm_layer_persist<<<NBLK_, 256, DSMEM>>>(W2h, XZ, H2);

    // Heads: mean = H2@Wm + bm ; cov = softplus(H2@Wc + bc)
    gemm_bias<0><<<dim3(DOUT_ / 64, BT_ / 128), 256>>>(H2, Wm, bm, out,        BT_, DOUT_, H_, DOUT_);
    gemm_bias<1><<<dim3(DOUT_ / 64, BT_ / 128), 256>>>(H2, Wc, bc, out + half, BT_, DOUT_, H_, DOUT_);
}

// round 5
// speedup vs baseline: 1.1213x; 1.1213x over previous
#include <cuda_runtime.h>
#include <math.h>

#define B_    32
#define T_    1024
#define H_    1024
#define FH_   4096
#define DIN_  256
#define DOUT_ 512
#define BT_   (B_*T_)
#define NBLK_ 128           // persistent-kernel grid; 1 block/SM (smem-limited)

// -------- scratch (static device globals; no allocation anywhere) ----------
__device__ float g_XZ[(size_t)BT_*FH_];   // 512 MB, reused for layer1 and layer2 xz
__device__ float g_H1[(size_t)BT_*H_];    // 128 MB
__device__ float g_H2[(size_t)BT_*H_];    // 128 MB

// grid barrier state (generation-relative => safe across graph replays)
__device__ unsigned          g_bar_count = 0;
__device__ volatile unsigned g_bar_gen   = 0;

__device__ __forceinline__ void grid_sync(unsigned* gen_local)
{
    __syncthreads();
    if (threadIdx.x == 0) {
        unsigned my = *gen_local;
        __threadfence();
        unsigned arr = atomicAdd(&g_bar_count, 1u);
        if (arr == NBLK_ - 1) {
            g_bar_count = 0;
            __threadfence();
            g_bar_gen = my + 1;
        } else {
            while (g_bar_gen == my) { }
        }
        *gen_local = my + 1;
    }
    __syncthreads();
}

// ---- cp.async helpers -----------------------------------------------------
__device__ __forceinline__ void cp_async16(void* sptr, const void* gptr)
{
    unsigned sa = (unsigned)__cvta_generic_to_shared(sptr);
    asm volatile("cp.async.cg.shared.global [%0], [%1], 16;" :: "r"(sa), "l"(gptr));
}
__device__ __forceinline__ void cp_commit()
{
    asm volatile("cp.async.commit_group;" ::: "memory");
}
template<int N> __device__ __forceinline__ void cp_wait()
{
    asm volatile("cp.async.wait_group %0;" :: "n"(N) : "memory");
}

// ---------------------------------------------------------------------------
// fp32 GEMM + bias (+ optional softplus). C[M,N] = A[M,K]@B[K,N] + bias.
// 128x128 tile, 256 threads, 8x8/thread, BK=16, double-buffered smem with
// register-staged global prefetch. M%128==0, N%128==0, K%16==0.
// ---------------------------------------------------------------------------
template<int EPI>
__global__ __launch_bounds__(256, 2)
void gemm_bias(const float* __restrict__ A, const float* __restrict__ Bm,
               const float* __restrict__ bias, float* __restrict__ C,
               int M, int N, int K, int ldc)
{
    __shared__ float As[2][16][132];   // A transposed: As[k][m]
    __shared__ float Bs[2][16][128];

    const int tid = threadIdx.x;
    const int tx  = tid & 15;        // n-group (8 cols)
    const int ty  = tid >> 4;        // m-group (8 rows)
    const int bm  = blockIdx.y * 128;
    const int bn  = blockIdx.x * 128;

    const int br  = tid >> 5;        // B-tile row (0..7)
    const int bc4 = tid & 31;        // B-tile col/4

    float  a_reg[8];
    float4 b_reg[2];

    // ---- prologue: load tile 0 into registers, store to buffer 0
    #pragma unroll
    for (int p = 0; p < 8; p++)
        a_reg[p] = A[(size_t)(bm + ty + p * 16) * K + tx];
    b_reg[0] = *(const float4*)&Bm[(size_t)br       * N + bn + bc4 * 4];
    b_reg[1] = *(const float4*)&Bm[(size_t)(br + 8) * N + bn + bc4 * 4];

    #pragma unroll
    for (int p = 0; p < 8; p++) As[0][tx][ty + p * 16] = a_reg[p];
    *(float4*)&Bs[0][br][bc4 * 4]     = b_reg[0];
    *(float4*)&Bs[0][br + 8][bc4 * 4] = b_reg[1];
    __syncthreads();

    float acc[8][8] = {};
    const int nk = K / 16;

    for (int c = 0; c < nk; c++) {
        const int buf = c & 1;

        if (c + 1 < nk) {   // prefetch next tile into registers (overlaps FMA)
            const int k0 = (c + 1) * 16;
            #pragma unroll
            for (int p = 0; p < 8; p++)
                a_reg[p] = A[(size_t)(bm + ty + p * 16) * K + k0 + tx];
            b_reg[0] = *(const float4*)&Bm[(size_t)(k0 + br)     * N + bn + bc4 * 4];
            b_reg[1] = *(const float4*)&Bm[(size_t)(k0 + br + 8) * N + bn + bc4 * 4];
        }

        #pragma unroll
        for (int k = 0; k < 16; k++) {
            float4 a0 = *(const float4*)&As[buf][k][ty * 8];
            float4 a1 = *(const float4*)&As[buf][k][ty * 8 + 4];
            float4 b0 = *(const float4*)&Bs[buf][k][tx * 8];
            float4 b1 = *(const float4*)&Bs[buf][k][tx * 8 + 4];
            float av[8] = {a0.x, a0.y, a0.z, a0.w, a1.x, a1.y, a1.z, a1.w};
            float bv[8] = {b0.x, b0.y, b0.z, b0.w, b1.x, b1.y, b1.z, b1.w};
            #pragma unroll
            for (int i = 0; i < 8; i++)
                #pragma unroll
                for (int j = 0; j < 8; j++)
                    acc[i][j] += av[i] * bv[j];
        }
        __syncthreads();

        if (c + 1 < nk) {
            #pragma unroll
            for (int p = 0; p < 8; p++) As[buf ^ 1][tx][ty + p * 16] = a_reg[p];
            *(float4*)&Bs[buf ^ 1][br][bc4 * 4]     = b_reg[0];
            *(float4*)&Bs[buf ^ 1][br + 8][bc4 * 4] = b_reg[1];
            __syncthreads();
        }
    }

    // ---- epilogue
    float4 bias0 = *(const float4*)&bias[bn + tx * 8];
    float4 bias1 = *(const float4*)&bias[bn + tx * 8 + 4];
    float bb[8] = {bias0.x, bias0.y, bias0.z, bias0.w, bias1.x, bias1.y, bias1.z, bias1.w};

    #pragma unroll
    for (int i = 0; i < 8; i++) {
        int row = bm + ty * 8 + i;
        float v[8];
        #pragma unroll
        for (int j = 0; j < 8; j++) {
            v[j] = acc[i][j] + bb[j];
            if (EPI == 1) v[j] = (v[j] > 20.f) ? v[j] : log1pf(expf(v[j]));
        }
        *(float4*)&C[(size_t)row * ldc + bn + tx * 8]     = make_float4(v[0], v[1], v[2], v[3]);
        *(float4*)&C[(size_t)row * ldc + bn + tx * 8 + 4] = make_float4(v[4], v[5], v[6], v[7]);
    }
}

// ---------------------------------------------------------------------------
// Persistent LSTM layer: whole T=1024 recurrence in ONE kernel.
// 128 blocks x 256 threads; block owns 8 hidden units (all 4 gate columns).
// Wh slice (128KB) in smem once; h_{t-1} read straight from this layer's own
// Hout via cp.async.cg double-buffered chunks (L2 latency overlapped with FMA).
// c lives in a register. One grid barrier per step.
// ---------------------------------------------------------------------------
__global__ __launch_bounds__(256, 1)
void lstm_layer_persist(const float* __restrict__ Wh,   // [H, 4H]
                        const float* __restrict__ XZ,   // [B*T, 4H] (bias folded)
                        float* __restrict__ Hout)       // [B, T, H]
{
    extern __shared__ float smem[];
    float4* w_s = (float4*)smem;                   // [1024][8] float4 = 128KB
    float*  h_s = smem + H_ * 8 * 4;               // [2][32*64]      = 16KB

    const int tid = threadIdx.x;
    const int ui  = tid & 7;
    const int b   = tid >> 3;
    const int u0  = blockIdx.x * 8;
    const int u   = u0 + ui;

    // one-time: load Wh slice, gate-interleaved: w_s[k][j] = {Wi,Wf,Wg,Wo}(unit u0+j)
    for (int lin = tid; lin < H_ * 8; lin += 256) {
        int k   = lin >> 3;
        int rem = lin & 7;
        int g   = rem >> 1;
        int hf  = rem & 1;
        float4 wv = *(const float4*)&Wh[(size_t)k * FH_ + g * H_ + u0 + hf * 4];
        float* base = (float*)&w_s[(size_t)k * 8];
        base[(hf * 4 + 0) * 4 + g] = wv.x;
        base[(hf * 4 + 1) * 4 + g] = wv.y;
        base[(hf * 4 + 2) * 4 + g] = wv.z;
        base[(hf * 4 + 3) * 4 + g] = wv.w;
    }

    float c_reg = 0.f;

    unsigned gen_local;
    if (tid == 0) gen_local = g_bar_gen;

    // chunk-staging thread map: 2 x (bl = lin>>4 in 0..31, kq = lin&15)
    const int bl0 = tid >> 4,        kq0 = tid & 15;
    const int bl1 = (tid + 256) >> 4, kq1 = tid & 15;

    // ---- t = 0: h0 = 0, so gates come from XZ alone (no matvec, no barrier yet)
    {
        const size_t row = (size_t)b * T_;
        const float* xz  = XZ + row * FH_;
        float zi = __ldg(&xz[u]);
        float zf = __ldg(&xz[H_ + u]);
        float zg = __ldg(&xz[2 * H_ + u]);
        float zo = __ldg(&xz[3 * H_ + u]);
        float iv = 1.f / (1.f + expf(-zi));
        float fv = 1.f / (1.f + expf(-zf));
        float gv = tanhf(zg);
        float ov = 1.f / (1.f + expf(-zo));
        c_reg = fv * 0.f + iv * gv;
        float hv = ov * tanhf(c_reg);
        Hout[row * H_ + u] = hv;
    }
    __threadfence();
    grid_sync(&gen_local);

    for (int t = 1; t < T_; t++) {
        const float* hprev = Hout + (size_t)(t - 1) * H_;  // + b*T_*H_ per row below

        // prefetch chunk 0 into buffer 0
        cp_async16(&h_s[bl0 * 64 + kq0 * 4],
                   hprev + (size_t)bl0 * T_ * H_ + kq0 * 4);
        cp_async16(&h_s[bl1 * 64 + kq1 * 4],
                   hprev + (size_t)bl1 * T_ * H_ + kq1 * 4);
        cp_commit();

        // xz gate inputs (latency hidden behind the chunk loop)
        const size_t row = (size_t)b * T_ + t;
        const float* xz  = XZ + row * FH_;
        float xi = __ldg(&xz[u]);
        float xf = __ldg(&xz[H_ + u]);
        float xg = __ldg(&xz[2 * H_ + u]);
        float xo = __ldg(&xz[3 * H_ + u]);

        float ai = 0.f, af = 0.f, ag = 0.f, ao = 0.f;

        #pragma unroll 1
        for (int c = 0; c < 16; c++) {
            const int buf = c & 1;
            if (c < 15) {   // prefetch chunk c+1
                const int k0n = (c + 1) * 64;
                float* dst = h_s + (buf ^ 1) * (32 * 64);
                cp_async16(&dst[bl0 * 64 + kq0 * 4],
                           hprev + (size_t)bl0 * T_ * H_ + k0n + kq0 * 4);
                cp_async16(&dst[bl1 * 64 + kq1 * 4],
                           hprev + (size_t)bl1 * T_ * H_ + k0n + kq1 * 4);
                cp_commit();
                cp_wait<1>();
            } else {
                cp_wait<0>();
            }
            __syncthreads();

            const float*  hrow = h_s + buf * (32 * 64) + b * 64;
            const float4* wrow = w_s + (size_t)c * 64 * 8 + ui;
            #pragma unroll
            for (int k4 = 0; k4 < 16; k4++) {
                float4 h4 = *(const float4*)&hrow[k4 * 4];
                float hv4[4] = {h4.x, h4.y, h4.z, h4.w};
                #pragma unroll
                for (int q = 0; q < 4; q++) {
                    float4 w = wrow[(size_t)(k4 * 4 + q) * 8];
                    float hv = hv4[q];
                    ai += hv * w.x;
                    af += hv * w.y;
                    ag += hv * w.z;
                    ao += hv * w.w;
                }
            }
            __syncthreads();
        }

        float zi = xi + ai;
        float zf = xf + af;
        float zg = xg + ag;
        float zo = xo + ao;

        float iv = 1.f / (1.f + expf(-zi));
        float fv = 1.f / (1.f + expf(-zf));
        float gv = tanhf(zg);
        float ov = 1.f / (1.f + expf(-zo));

        c_reg = fv * c_reg + iv * gv;
        float hv = ov * tanhf(c_reg);
        Hout[row * H_ + u] = hv;

        __threadfence();
        grid_sync(&gen_local);
    }
}

// ---------------------------------------------------------------------------
extern "C" void kernel_launch(void* const* d_in, const int* in_sizes, int n_in,
                              void* d_out, int out_size)
{
    const float* obs = (const float*)d_in[0];
    const float* W1x = (const float*)d_in[1];
    const float* W1h = (const float*)d_in[2];
    const float* b1  = (const float*)d_in[3];
    const float* W2x = (const float*)d_in[4];
    const float* W2h = (const float*)d_in[5];
    const float* b2  = (const float*)d_in[6];
    const float* Wm  = (const float*)d_in[7];
    const float* bm  = (const float*)d_in[8];
    const float* Wc  = (const float*)d_in[9];
    const float* bc  = (const float*)d_in[10];

    float *XZ, *H1, *H2;
    cudaGetSymbolAddress((void**)&XZ, g_XZ);
    cudaGetSymbolAddress((void**)&H1, g_H1);
    cudaGetSymbolAddress((void**)&H2, g_H2);

    float* out = (float*)d_out;
    size_t half = (size_t)out_size / 2;   // mean | cov

    const int DSMEM = H_ * 8 * 4 * (int)sizeof(float)     // W slice 128KB
                    + 2 * 32 * 64 * (int)sizeof(float);   // h double buffer 16KB
    cudaFuncSetAttribute(lstm_layer_persist,
                         cudaFuncAttributeMaxDynamicSharedMemorySize, DSMEM);

    // XZ1 = obs @ W1x + b1
    gemm_bias<0><<<dim3(FH_ / 128, BT_ / 128), 256>>>(obs, W1x, b1, XZ, BT_, FH_, DIN_, FH_);

    // Layer 1 recurrence (persistent)
    lstm_layer_persist<<<NBLK_, 256, DSMEM>>>(W1h, XZ, H1);

    // XZ2 = H1 @ W2x + b2  (reuse XZ buffer)
    gemm_bias<0><<<dim3(FH_ / 128, BT_ / 128), 256>>>(H1, W2x, b2, XZ, BT_, FH_, H_, FH_);

    // Layer 2 recurrence
    lstm_layer_persist<<<NBLK_, 256, DSMEM>>>(W2h, XZ, H2);

    // Heads: mean = H2@Wm + bm ; cov = softplus(H2@Wc + bc)
    gemm_bias<0><<<dim3(DOUT_ / 128, BT_ / 128), 256>>>(H2, Wm, bm, out,        BT_, DOUT_, H_, DOUT_);
    gemm_bias<1><<<dim3(DOUT_ / 128, BT_ / 128), 256>>>(H2, Wc, bc, out + half, BT_, DOUT_, H_, DOUT_);
}

// round 6
// speedup vs baseline: 1.6128x; 1.4383x over previous
#include <cuda_runtime.h>
#include <math.h>

#define B_    32
#define T_    1024
#define H_    1024
#define FH_   4096
#define DIN_  256
#define DOUT_ 512
#define BT_   (B_*T_)
#define NBLK_ 128           // persistent-kernel grid; 1 block/SM (smem-limited)

typedef unsigned long long ull;

// -------- scratch (static device globals; no allocation anywhere) ----------
__device__ float g_XZ[(size_t)BT_*FH_];   // 512 MB, reused for layer1 and layer2 xz
__device__ float g_H1[(size_t)BT_*H_];    // 128 MB
__device__ float g_H2[(size_t)BT_*H_];    // 128 MB

// grid barrier state (generation-relative => safe across graph replays)
__device__ unsigned          g_bar_count = 0;
__device__ volatile unsigned g_bar_gen   = 0;

__device__ __forceinline__ void grid_sync(unsigned* gen_local)
{
    __syncthreads();
    if (threadIdx.x == 0) {
        unsigned my = *gen_local;
        __threadfence();
        unsigned arr = atomicAdd(&g_bar_count, 1u);
        if (arr == NBLK_ - 1) {
            g_bar_count = 0;
            __threadfence();
            g_bar_gen = my + 1;
        } else {
            while (g_bar_gen == my) { }
        }
        *gen_local = my + 1;
    }
    __syncthreads();
}

// ---- packed f32x2 helpers (sm_103a FFMA2 path) ----------------------------
__device__ __forceinline__ ull splat2(float x)
{
    ull r; unsigned xi = __float_as_uint(x);
    asm("mov.b64 %0, {%1, %1};" : "=l"(r) : "r"(xi));
    return r;
}
__device__ __forceinline__ void ffma2(ull& d, ull a, ull b)
{
    asm("fma.rn.f32x2 %0, %1, %2, %0;" : "+l"(d) : "l"(a), "l"(b));
}
__device__ __forceinline__ void addf2(ull& d, ull a)
{
    asm("add.rn.f32x2 %0, %0, %1;" : "+l"(d) : "l"(a));
}
__device__ __forceinline__ void unpack2(ull v, float& lo, float& hi)
{
    unsigned a, b;
    asm("mov.b64 {%0, %1}, %2;" : "=r"(a), "=r"(b) : "l"(v));
    lo = __uint_as_float(a); hi = __uint_as_float(b);
}

// ---- cp.async helpers -----------------------------------------------------
__device__ __forceinline__ void cp_async16(void* sptr, const void* gptr)
{
    unsigned sa = (unsigned)__cvta_generic_to_shared(sptr);
    asm volatile("cp.async.cg.shared.global [%0], [%1], 16;" :: "r"(sa), "l"(gptr));
}
__device__ __forceinline__ void cp_commit()
{
    asm volatile("cp.async.commit_group;" ::: "memory");
}
template<int N> __device__ __forceinline__ void cp_wait()
{
    asm volatile("cp.async.wait_group %0;" :: "n"(N) : "memory");
}

// ---------------------------------------------------------------------------
// fp32 GEMM + bias (+ optional softplus), FFMA2 inner kernel.
// C[M,N] = A[M,K]@B[K,N] + bias.  128x128 tile, 256 threads, 8x8/thread,
// BK=16, double-buffered smem with register-staged global prefetch.
// ---------------------------------------------------------------------------
template<int EPI>
__global__ __launch_bounds__(256, 2)
void gemm_bias(const float* __restrict__ A, const float* __restrict__ Bm,
               const float* __restrict__ bias, float* __restrict__ C,
               int M, int N, int K, int ldc)
{
    __shared__ __align__(16) float As[2][16][132];   // A transposed: As[k][m]
    __shared__ __align__(16) float Bs[2][16][128];

    const int tid = threadIdx.x;
    const int tx  = tid & 15;        // n-group (8 cols)
    const int ty  = tid >> 4;        // m-group (8 rows)
    const int bm  = blockIdx.y * 128;
    const int bn  = blockIdx.x * 128;

    const int br  = tid >> 5;        // B-tile row (0..7)
    const int bc4 = tid & 31;        // B-tile col/4

    float  a_reg[8];
    float4 b_reg[2];

    // ---- prologue: tile 0
    #pragma unroll
    for (int p = 0; p < 8; p++)
        a_reg[p] = A[(size_t)(bm + ty + p * 16) * K + tx];
    b_reg[0] = *(const float4*)&Bm[(size_t)br       * N + bn + bc4 * 4];
    b_reg[1] = *(const float4*)&Bm[(size_t)(br + 8) * N + bn + bc4 * 4];

    #pragma unroll
    for (int p = 0; p < 8; p++) As[0][tx][ty + p * 16] = a_reg[p];
    *(float4*)&Bs[0][br][bc4 * 4]     = b_reg[0];
    *(float4*)&Bs[0][br + 8][bc4 * 4] = b_reg[1];
    __syncthreads();

    ull acc2[8][4] = {};              // each = {c[2jp], c[2jp+1]}
    const int nk = K / 16;

    for (int c = 0; c < nk; c++) {
        const int buf = c & 1;

        if (c + 1 < nk) {   // prefetch next tile into registers (overlaps FMA)
            const int k0 = (c + 1) * 16;
            #pragma unroll
            for (int p = 0; p < 8; p++)
                a_reg[p] = A[(size_t)(bm + ty + p * 16) * K + k0 + tx];
            b_reg[0] = *(const float4*)&Bm[(size_t)(k0 + br)     * N + bn + bc4 * 4];
            b_reg[1] = *(const float4*)&Bm[(size_t)(k0 + br + 8) * N + bn + bc4 * 4];
        }

        #pragma unroll
        for (int k = 0; k < 16; k++) {
            float4 a0 = *(const float4*)&As[buf][k][ty * 8];
            float4 a1 = *(const float4*)&As[buf][k][ty * 8 + 4];
            float av[8] = {a0.x, a0.y, a0.z, a0.w, a1.x, a1.y, a1.z, a1.w};
            ull as2[8];
            #pragma unroll
            for (int i = 0; i < 8; i++) as2[i] = splat2(av[i]);

            ulonglong2 bq0 = *(const ulonglong2*)&Bs[buf][k][tx * 8];
            ulonglong2 bq1 = *(const ulonglong2*)&Bs[buf][k][tx * 8 + 4];
            ull bv[4] = {bq0.x, bq0.y, bq1.x, bq1.y};

            #pragma unroll
            for (int i = 0; i < 8; i++)
                #pragma unroll
                for (int jp = 0; jp < 4; jp++)
                    ffma2(acc2[i][jp], as2[i], bv[jp]);
        }
        __syncthreads();

        if (c + 1 < nk) {
            #pragma unroll
            for (int p = 0; p < 8; p++) As[buf ^ 1][tx][ty + p * 16] = a_reg[p];
            *(float4*)&Bs[buf ^ 1][br][bc4 * 4]     = b_reg[0];
            *(float4*)&Bs[buf ^ 1][br + 8][bc4 * 4] = b_reg[1];
            __syncthreads();
        }
    }

    // ---- epilogue
    float4 bias0 = *(const float4*)&bias[bn + tx * 8];
    float4 bias1 = *(const float4*)&bias[bn + tx * 8 + 4];
    float bb[8] = {bias0.x, bias0.y, bias0.z, bias0.w, bias1.x, bias1.y, bias1.z, bias1.w};

    #pragma unroll
    for (int i = 0; i < 8; i++) {
        int row = bm + ty * 8 + i;
        float v[8];
        #pragma unroll
        for (int jp = 0; jp < 4; jp++)
            unpack2(acc2[i][jp], v[2 * jp], v[2 * jp + 1]);
        #pragma unroll
        for (int j = 0; j < 8; j++) {
            v[j] += bb[j];
            if (EPI == 1) v[j] = (v[j] > 20.f) ? v[j] : log1pf(expf(v[j]));
        }
        *(float4*)&C[(size_t)row * ldc + bn + tx * 8]     = make_float4(v[0], v[1], v[2], v[3]);
        *(float4*)&C[(size_t)row * ldc + bn + tx * 8 + 4] = make_float4(v[4], v[5], v[6], v[7]);
    }
}

// ---------------------------------------------------------------------------
// Persistent LSTM layer, v3: 512 threads/block (4 warps/SMSP), k-reduction
// split 4 ways (kh), 2 batch rows per thread, FFMA2 gate math.
// Block owns 8 hidden units (all 4 gate columns). Wh slice (128KB) in smem
// once. h_{t-1} read from this layer's own Hout via cp.async double buffer.
// Cross-kh partials reduced through smem; c lives in kh==0 thread registers.
// ---------------------------------------------------------------------------
__global__ __launch_bounds__(512, 1)
void lstm_layer_persist(const float* __restrict__ Wh,   // [H, 4H]
                        const float* __restrict__ XZ,   // [B*T, 4H] (bias folded)
                        float* __restrict__ Hout)       // [B, T, H]
{
    extern __shared__ float smem[];
    float4*     w_s   = (float4*)smem;                       // [1024][8] f4 = 128KB
    float*      h_s   = smem + H_ * 8 * 4;                   // [2][4][32][64]  64KB
    ulonglong2* part2 = (ulonglong2*)(smem + 49152);         // [3][32][8]      12KB

    const int tid = threadIdx.x;
    const int kh  = tid >> 7;        // 0..3  : k quarter
    const int l   = tid & 127;
    const int ui  = l & 7;           // unit within block
    const int bp  = l >> 3;          // batch pair 0..15
    const int b0  = bp * 2;
    const int b1  = b0 + 1;
    const int u0  = blockIdx.x * 8;
    const int u   = u0 + ui;

    // one-time: load Wh slice gate-interleaved: w_s[k][j] = {Wi,Wf,Wg,Wo}(unit u0+j)
    for (int lin = tid; lin < H_ * 8; lin += 512) {
        int k   = lin >> 3;
        int rem = lin & 7;
        int g   = rem >> 1;
        int hf  = rem & 1;
        float4 wv = *(const float4*)&Wh[(size_t)k * FH_ + g * H_ + u0 + hf * 4];
        float* base = (float*)&w_s[(size_t)k * 8];
        base[(hf * 4 + 0) * 4 + g] = wv.x;
        base[(hf * 4 + 1) * 4 + g] = wv.y;
        base[(hf * 4 + 2) * 4 + g] = wv.z;
        base[(hf * 4 + 3) * 4 + g] = wv.w;
    }

    float c0 = 0.f, c1 = 0.f;        // cell state (kh==0 threads only)

    unsigned gen_local;
    if (tid == 0) gen_local = g_bar_gen;

    // ---- t = 0: h0 = 0 -> gates from XZ alone
    if (kh == 0) {
        #pragma unroll
        for (int s = 0; s < 2; s++) {
            int bb = s ? b1 : b0;
            const float* xz = XZ + (size_t)bb * T_ * FH_;
            float zi = __ldg(&xz[u]);
            float zf = __ldg(&xz[H_ + u]);
            float zg = __ldg(&xz[2 * H_ + u]);
            float zo = __ldg(&xz[3 * H_ + u]);
            float iv = 1.f / (1.f + expf(-zi));
            float gv = tanhf(zg);
            float ov = 1.f / (1.f + expf(-zo));
            (void)zf;
            float cc = iv * gv;                 // f*c0 = 0
            if (s) c1 = cc; else c0 = cc;
            Hout[(size_t)bb * T_ * H_ + u] = ov * tanhf(cc);
        }
    }
    __threadfence();
    grid_sync(&gen_local);

    for (int t = 1; t < T_; t++) {
        const float* hbase = Hout + (size_t)(t - 1) * H_;    // + b*T_*H_ per row

        // xz gate inputs for this step (kh==0 only; hidden behind the k loop)
        float x0[4], x1[4];
        if (kh == 0) {
            const float* xz0 = XZ + ((size_t)b0 * T_ + t) * FH_;
            const float* xz1 = XZ + ((size_t)b1 * T_ + t) * FH_;
            x0[0] = __ldg(&xz0[u]);          x1[0] = __ldg(&xz1[u]);
            x0[1] = __ldg(&xz0[H_ + u]);     x1[1] = __ldg(&xz1[H_ + u]);
            x0[2] = __ldg(&xz0[2 * H_ + u]); x1[2] = __ldg(&xz1[2 * H_ + u]);
            x0[3] = __ldg(&xz0[3 * H_ + u]); x1[3] = __ldg(&xz1[3 * H_ + u]);
        }

        ull a0if = 0, a0go = 0, a1if = 0, a1go = 0;

        // stage chunk 0 of this kh quarter into buffer 0
        {
            const int k0 = kh * 256;
            float* dst = h_s + (size_t)(0 * 4 + kh) * 32 * 64;
            #pragma unroll
            for (int i = 0; i < 4; i++) {
                int idx = l + i * 128;
                int bs = idx >> 4, q = idx & 15;
                cp_async16(&dst[bs * 64 + q * 4],
                           hbase + (size_t)bs * T_ * H_ + k0 + q * 4);
            }
            cp_commit();
        }

        #pragma unroll 1
        for (int j = 0; j < 4; j++) {
            const int buf = j & 1;
            if (j < 3) {   // prefetch chunk j+1 into other buffer
                const int k0n = kh * 256 + (j + 1) * 64;
                float* dst = h_s + (size_t)((buf ^ 1) * 4 + kh) * 32 * 64;
                #pragma unroll
                for (int i = 0; i < 4; i++) {
                    int idx = l + i * 128;
                    int bs = idx >> 4, q = idx & 15;
                    cp_async16(&dst[bs * 64 + q * 4],
                               hbase + (size_t)bs * T_ * H_ + k0n + q * 4);
                }
                cp_commit();
                cp_wait<1>();
            } else {
                cp_wait<0>();
            }
            __syncthreads();

            const float*  hrow0 = h_s + ((size_t)(buf * 4 + kh) * 32 + b0) * 64;
            const float*  hrow1 = hrow0 + 64;
            const float4* wbase = w_s + (size_t)(kh * 256 + j * 64) * 8 + ui;

            #pragma unroll
            for (int k4 = 0; k4 < 16; k4++) {
                float4 h40 = *(const float4*)&hrow0[k4 * 4];
                float4 h41 = *(const float4*)&hrow1[k4 * 4];
                float h0a[4] = {h40.x, h40.y, h40.z, h40.w};
                float h1a[4] = {h41.x, h41.y, h41.z, h41.w};
                #pragma unroll
                for (int q = 0; q < 4; q++) {
                    ulonglong2 wv = *(const ulonglong2*)&wbase[(size_t)(k4 * 4 + q) * 8];
                    ull s0 = splat2(h0a[q]);
                    ull s1 = splat2(h1a[q]);
                    ffma2(a0if, s0, wv.x);
                    ffma2(a0go, s0, wv.y);
                    ffma2(a1if, s1, wv.x);
                    ffma2(a1go, s1, wv.y);
                }
            }
            __syncthreads();
        }

        // ---- cross-kh reduction
        if (kh != 0) {
            ulonglong2* p = part2 + (size_t)(kh - 1) * 256;
            ulonglong2 v0; v0.x = a0if; v0.y = a0go;
            ulonglong2 v1; v1.x = a1if; v1.y = a1go;
            p[b0 * 8 + ui] = v0;
            p[b1 * 8 + ui] = v1;
        }
        __syncthreads();

        if (kh == 0) {
            #pragma unroll
            for (int r = 0; r < 3; r++) {
                ulonglong2 q0 = part2[r * 256 + b0 * 8 + ui];
                ulonglong2 q1 = part2[r * 256 + b1 * 8 + ui];
                addf2(a0if, q0.x); addf2(a0go, q0.y);
                addf2(a1if, q1.x); addf2(a1go, q1.y);
            }
            float zi0, zf0, zg0, zo0, zi1, zf1, zg1, zo1;
            unpack2(a0if, zi0, zf0); unpack2(a0go, zg0, zo0);
            unpack2(a1if, zi1, zf1); unpack2(a1go, zg1, zo1);
            zi0 += x0[0]; zf0 += x0[1]; zg0 += x0[2]; zo0 += x0[3];
            zi1 += x1[0]; zf1 += x1[1]; zg1 += x1[2]; zo1 += x1[3];

            float iv0 = 1.f / (1.f + expf(-zi0));
            float fv0 = 1.f / (1.f + expf(-zf0));
            float gv0 = tanhf(zg0);
            float ov0 = 1.f / (1.f + expf(-zo0));
            c0 = fv0 * c0 + iv0 * gv0;
            Hout[((size_t)b0 * T_ + t) * H_ + u] = ov0 * tanhf(c0);

            float iv1 = 1.f / (1.f + expf(-zi1));
            float fv1 = 1.f / (1.f + expf(-zf1));
            float gv1 = tanhf(zg1);
            float ov1 = 1.f / (1.f + expf(-zo1));
            c1 = fv1 * c1 + iv1 * gv1;
            Hout[((size_t)b1 * T_ + t) * H_ + u] = ov1 * tanhf(c1);
        }

        __threadfence();
        grid_sync(&gen_local);
    }
}

// ---------------------------------------------------------------------------
extern "C" void kernel_launch(void* const* d_in, const int* in_sizes, int n_in,
                              void* d_out, int out_size)
{
    const float* obs = (const float*)d_in[0];
    const float* W1x = (const float*)d_in[1];
    const float* W1h = (const float*)d_in[2];
    const float* b1  = (const float*)d_in[3];
    const float* W2x = (const float*)d_in[4];
    const float* W2h = (const float*)d_in[5];
    const float* b2  = (const float*)d_in[6];
    const float* Wm  = (const float*)d_in[7];
    const float* bm  = (const float*)d_in[8];
    const float* Wc  = (const float*)d_in[9];
    const float* bc  = (const float*)d_in[10];

    float *XZ, *H1, *H2;
    cudaGetSymbolAddress((void**)&XZ, g_XZ);
    cudaGetSymbolAddress((void**)&H1, g_H1);
    cudaGetSymbolAddress((void**)&H2, g_H2);

    float* out = (float*)d_out;
    size_t half = (size_t)out_size / 2;   // mean | cov

    const int DSMEM = H_ * 8 * 4 * (int)sizeof(float)     // W slice   128KB
                    + 2 * 4 * 32 * 64 * (int)sizeof(float)// h dbl buf  64KB
                    + 3 * 32 * 8 * 16;                    // partials   12KB
    cudaFuncSetAttribute(lstm_layer_persist,
                         cudaFuncAttributeMaxDynamicSharedMemorySize, DSMEM);

    // XZ1 = obs @ W1x + b1
    gemm_bias<0><<<dim3(FH_ / 128, BT_ / 128), 256>>>(obs, W1x, b1, XZ, BT_, FH_, DIN_, FH_);

    // Layer 1 recurrence (persistent)
    lstm_layer_persist<<<NBLK_, 512, DSMEM>>>(W1h, XZ, H1);

    // XZ2 = H1 @ W2x + b2  (reuse XZ buffer)
    gemm_bias<0><<<dim3(FH_ / 128, BT_ / 128), 256>>>(H1, W2x, b2, XZ, BT_, FH_, H_, FH_);

    // Layer 2 recurrence
    lstm_layer_persist<<<NBLK_, 512, DSMEM>>>(W2h, XZ, H2);

    // Heads: mean = H2@Wm + bm ; cov = softplus(H2@Wc + bc)
    gemm_bias<0><<<dim3(DOUT_ / 128, BT_ / 128), 256>>>(H2, Wm, bm, out,        BT_, DOUT_, H_, DOUT_);
    gemm_bias<1><<<dim3(DOUT_ / 128, BT_ / 128), 256>>>(H2, Wc, bc, out + half, BT_, DOUT_, H_, DOUT_);
}

// round 7
// speedup vs baseline: 1.7255x; 1.0699x over previous
#include <cuda_runtime.h>
#include <math.h>

#define B_    32
#define T_    1024
#define H_    1024
#define FH_   4096
#define DIN_  256
#define DOUT_ 512
#define BT_   (B_*T_)
#define NBLK_ 128           // persistent-kernel grid; 1 block/SM (smem-limited)
#define NTH_  1024

typedef unsigned long long ull;

// -------- scratch (static device globals; no allocation anywhere) ----------
__device__ float g_XZ[(size_t)BT_*FH_];   // 512 MB, reused for layer1 and layer2 xz
__device__ float g_H1[(size_t)BT_*H_];    // 128 MB
__device__ float g_H2[(size_t)BT_*H_];    // 128 MB
__device__ float g_hT[2][H_*B_];          // transposed hidden mirror: hT[par][k*32+b]

// grid barrier state (generation-relative => safe across graph replays)
__device__ unsigned          g_bar_count = 0;
__device__ volatile unsigned g_bar_gen   = 0;

__device__ __forceinline__ void grid_sync(unsigned* gen_local)
{
    __syncthreads();
    if (threadIdx.x == 0) {
        unsigned my = *gen_local;
        __threadfence();
        unsigned arr = atomicAdd(&g_bar_count, 1u);
        if (arr == NBLK_ - 1) {
            g_bar_count = 0;
            __threadfence();
            g_bar_gen = my + 1;
        } else {
            while (g_bar_gen == my) { }
        }
        *gen_local = my + 1;
    }
    __syncthreads();
}

// ---- packed f32x2 helpers (sm_103a FFMA2 path) ----------------------------
__device__ __forceinline__ ull splat2(float x)
{
    ull r; unsigned xi = __float_as_uint(x);
    asm("mov.b64 %0, {%1, %1};" : "=l"(r) : "r"(xi));
    return r;
}
__device__ __forceinline__ void ffma2(ull& d, ull a, ull b)
{
    asm("fma.rn.f32x2 %0, %1, %2, %0;" : "+l"(d) : "l"(a), "l"(b));
}
__device__ __forceinline__ void addf2(ull& d, ull a)
{
    asm("add.rn.f32x2 %0, %0, %1;" : "+l"(d) : "l"(a));
}
__device__ __forceinline__ void unpack2(ull v, float& lo, float& hi)
{
    unsigned a, b;
    asm("mov.b64 {%0, %1}, %2;" : "=r"(a), "=r"(b) : "l"(v));
    lo = __uint_as_float(a); hi = __uint_as_float(b);
}

// ---- cp.async helpers -----------------------------------------------------
__device__ __forceinline__ void cp_async16(void* sptr, const void* gptr)
{
    unsigned sa = (unsigned)__cvta_generic_to_shared(sptr);
    asm volatile("cp.async.cg.shared.global [%0], [%1], 16;" :: "r"(sa), "l"(gptr));
}
__device__ __forceinline__ void cp_commit()
{
    asm volatile("cp.async.commit_group;" ::: "memory");
}
template<int N> __device__ __forceinline__ void cp_wait()
{
    asm volatile("cp.async.wait_group %0;" :: "n"(N) : "memory");
}

// ---------------------------------------------------------------------------
// fp32 GEMM + bias (+ optional softplus), FFMA2 inner kernel. (unchanged R6)
// ---------------------------------------------------------------------------
template<int EPI>
__global__ __launch_bounds__(256, 2)
void gemm_bias(const float* __restrict__ A, const float* __restrict__ Bm,
               const float* __restrict__ bias, float* __restrict__ C,
               int M, int N, int K, int ldc)
{
    __shared__ __align__(16) float As[2][16][132];
    __shared__ __align__(16) float Bs[2][16][128];

    const int tid = threadIdx.x;
    const int tx  = tid & 15;
    const int ty  = tid >> 4;
    const int bm  = blockIdx.y * 128;
    const int bn  = blockIdx.x * 128;

    const int br  = tid >> 5;
    const int bc4 = tid & 31;

    float  a_reg[8];
    float4 b_reg[2];

    #pragma unroll
    for (int p = 0; p < 8; p++)
        a_reg[p] = A[(size_t)(bm + ty + p * 16) * K + tx];
    b_reg[0] = *(const float4*)&Bm[(size_t)br       * N + bn + bc4 * 4];
    b_reg[1] = *(const float4*)&Bm[(size_t)(br + 8) * N + bn + bc4 * 4];

    #pragma unroll
    for (int p = 0; p < 8; p++) As[0][tx][ty + p * 16] = a_reg[p];
    *(float4*)&Bs[0][br][bc4 * 4]     = b_reg[0];
    *(float4*)&Bs[0][br + 8][bc4 * 4] = b_reg[1];
    __syncthreads();

    ull acc2[8][4] = {};
    const int nk = K / 16;

    for (int c = 0; c < nk; c++) {
        const int buf = c & 1;

        if (c + 1 < nk) {
            const int k0 = (c + 1) * 16;
            #pragma unroll
            for (int p = 0; p < 8; p++)
                a_reg[p] = A[(size_t)(bm + ty + p * 16) * K + k0 + tx];
            b_reg[0] = *(const float4*)&Bm[(size_t)(k0 + br)     * N + bn + bc4 * 4];
            b_reg[1] = *(const float4*)&Bm[(size_t)(k0 + br + 8) * N + bn + bc4 * 4];
        }

        #pragma unroll
        for (int k = 0; k < 16; k++) {
            float4 a0 = *(const float4*)&As[buf][k][ty * 8];
            float4 a1 = *(const float4*)&As[buf][k][ty * 8 + 4];
            float av[8] = {a0.x, a0.y, a0.z, a0.w, a1.x, a1.y, a1.z, a1.w};
            ull as2[8];
            #pragma unroll
            for (int i = 0; i < 8; i++) as2[i] = splat2(av[i]);

            ulonglong2 bq0 = *(const ulonglong2*)&Bs[buf][k][tx * 8];
            ulonglong2 bq1 = *(const ulonglong2*)&Bs[buf][k][tx * 8 + 4];
            ull bv[4] = {bq0.x, bq0.y, bq1.x, bq1.y};

            #pragma unroll
            for (int i = 0; i < 8; i++)
                #pragma unroll
                for (int jp = 0; jp < 4; jp++)
                    ffma2(acc2[i][jp], as2[i], bv[jp]);
        }
        __syncthreads();

        if (c + 1 < nk) {
            #pragma unroll
            for (int p = 0; p < 8; p++) As[buf ^ 1][tx][ty + p * 16] = a_reg[p];
            *(float4*)&Bs[buf ^ 1][br][bc4 * 4]     = b_reg[0];
            *(float4*)&Bs[buf ^ 1][br + 8][bc4 * 4] = b_reg[1];
            __syncthreads();
        }
    }

    float4 bias0 = *(const float4*)&bias[bn + tx * 8];
    float4 bias1 = *(const float4*)&bias[bn + tx * 8 + 4];
    float bb[8] = {bias0.x, bias0.y, bias0.z, bias0.w, bias1.x, bias1.y, bias1.z, bias1.w};

    #pragma unroll
    for (int i = 0; i < 8; i++) {
        int row = bm + ty * 8 + i;
        float v[8];
        #pragma unroll
        for (int jp = 0; jp < 4; jp++)
            unpack2(acc2[i][jp], v[2 * jp], v[2 * jp + 1]);
        #pragma unroll
        for (int j = 0; j < 8; j++) {
            v[j] += bb[j];
            if (EPI == 1) v[j] = (v[j] > 20.f) ? v[j] : log1pf(expf(v[j]));
        }
        *(float4*)&C[(size_t)row * ldc + bn + tx * 8]     = make_float4(v[0], v[1], v[2], v[3]);
        *(float4*)&C[(size_t)row * ldc + bn + tx * 8 + 4] = make_float4(v[4], v[5], v[6], v[7]);
    }
}

// ---------------------------------------------------------------------------
// Persistent LSTM layer v4: 1024 threads, 8 warps/SMSP.
// tid = sub*64 + bg*8 + ui :  sub(16) k-subrange, bg(8) row-quad, ui(8) unit.
// Per phase p (4 phases of 256 k): chunk hT[k][b] (32KB) staged via cp.async
// double-buffer; thread accumulates its 16 k x 4 rows x 4 gates with FFMA2.
// Partials (16 sub-slots) land in the h-staging smem (64KB), reduced by 256
// reducer threads (one per (u,b)); c-state lives in reducer registers.
// ---------------------------------------------------------------------------
__global__ __launch_bounds__(NTH_, 1)
void lstm_layer_persist(const float* __restrict__ Wh,   // [H, 4H]
                        const float* __restrict__ XZ,   // [B*T, 4H] (bias folded)
                        float* __restrict__ Hout)       // [B, T, H]
{
    extern __shared__ float smem[];
    float4*     w_s  = (float4*)smem;                 // [1024][8] float4 = 128KB
    float*      hch  = smem + H_ * 8 * 4;             // 2 x [256][32]    =  64KB
    ulonglong2* part = (ulonglong2*)hch;              // aliased after compute: 16 x 256 x 16B

    const int tid = threadIdx.x;
    const int ui  = tid & 7;
    const int bg  = (tid >> 3) & 7;
    const int sub = tid >> 6;          // 0..15
    const int b0  = bg * 4;
    const int u0  = blockIdx.x * 8;

    // one-time: load Wh slice gate-interleaved: w_s[k][j] = {Wi,Wf,Wg,Wo}(unit u0+j)
    for (int lin = tid; lin < H_ * 8; lin += NTH_) {
        int k   = lin >> 3;
        int rem = lin & 7;
        int g   = rem >> 1;
        int hf  = rem & 1;
        float4 wv = *(const float4*)&Wh[(size_t)k * FH_ + g * H_ + u0 + hf * 4];
        float* base = (float*)&w_s[(size_t)k * 8];
        base[(hf * 4 + 0) * 4 + g] = wv.x;
        base[(hf * 4 + 1) * 4 + g] = wv.y;
        base[(hf * 4 + 2) * 4 + g] = wv.z;
        base[(hf * 4 + 3) * 4 + g] = wv.w;
    }

    // reducer identity: tid<256 -> (u_r = u0 + (tid&7), b_r = tid>>3)
    const int urow = tid & 7;
    const int b_r  = tid >> 3;         // valid only when tid < 256
    const int u_r  = u0 + urow;
    float c_reg = 0.f;                 // cell state (reducers only)

    unsigned gen_local;
    if (tid == 0) gen_local = g_bar_gen;

    // ---- t = 0: h0 = 0 -> gates from XZ alone (reducers only)
    if (tid < 256) {
        const float* xz = XZ + (size_t)b_r * T_ * FH_ + u_r;
        float zi = __ldg(&xz[0]);
        float zg = __ldg(&xz[2 * H_]);
        float zo = __ldg(&xz[3 * H_]);
        float iv = 1.f / (1.f + expf(-zi));
        float gv = tanhf(zg);
        float ov = 1.f / (1.f + expf(-zo));
        c_reg = iv * gv;
        float hv = ov * tanhf(c_reg);
        Hout[(size_t)b_r * T_ * H_ + u_r] = hv;
        g_hT[0][u_r * 32 + b_r] = hv;
    }
    __threadfence();
    grid_sync(&gen_local);

    for (int t = 1; t < T_; t++) {
        const float* hTsrc = g_hT[(t - 1) & 1];

        // reducers: prefetch xz gate inputs (hidden behind the phase loop)
        float x_i, x_f, x_g, x_o;
        if (tid < 256) {
            const float* xz = XZ + ((size_t)b_r * T_ + t) * FH_ + u_r;
            x_i = __ldg(&xz[0]);
            x_f = __ldg(&xz[H_]);
            x_g = __ldg(&xz[2 * H_]);
            x_o = __ldg(&xz[3 * H_]);
        }

        ull accif[4] = {}, accgo[4] = {};

        // stage phase 0 into buffer 0 (32KB: each thread 2 x 16B)
        cp_async16(hch + tid * 4,        hTsrc + tid * 4);
        cp_async16(hch + tid * 4 + 4096, hTsrc + tid * 4 + 4096);
        cp_commit();

        #pragma unroll 1
        for (int p = 0; p < 4; p++) {
            const int buf = p & 1;
            if (p < 3) {   // prefetch phase p+1 into other buffer
                float*       dst = hch + ((buf ^ 1) * 8192);
                const float* src = hTsrc + (p + 1) * 8192;
                cp_async16(dst + tid * 4,        src + tid * 4);
                cp_async16(dst + tid * 4 + 4096, src + tid * 4 + 4096);
                cp_commit();
                cp_wait<1>();
            } else {
                cp_wait<0>();
            }
            __syncthreads();

            const float*  hb    = hch + buf * 8192 + b0;
            const float4* wbase = w_s + ((size_t)p * 256 + sub * 16) * 8 + ui;

            #pragma unroll
            for (int j = 0; j < 16; j++) {
                float4 h4 = *(const float4*)&hb[(sub * 16 + j) * 32];
                ulonglong2 wv = *(const ulonglong2*)&wbase[(size_t)j * 8];
                ull s;
                s = splat2(h4.x); ffma2(accif[0], s, wv.x); ffma2(accgo[0], s, wv.y);
                s = splat2(h4.y); ffma2(accif[1], s, wv.x); ffma2(accgo[1], s, wv.y);
                s = splat2(h4.z); ffma2(accif[2], s, wv.x); ffma2(accgo[2], s, wv.y);
                s = splat2(h4.w); ffma2(accif[3], s, wv.x); ffma2(accgo[3], s, wv.y);
            }
            __syncthreads();
        }

        // ---- dump partials (h staging buffer is free now)
        #pragma unroll
        for (int r = 0; r < 4; r++) {
            ulonglong2 v; v.x = accif[r]; v.y = accgo[r];
            part[sub * 256 + ui * 32 + b0 + r] = v;
        }
        __syncthreads();

        // ---- reduce + gates + writes (256 reducers)
        if (tid < 256) {
            ulonglong2 v0 = part[urow * 32 + b_r];
            ull aif = v0.x, ago = v0.y;
            #pragma unroll
            for (int q = 1; q < 16; q++) {
                ulonglong2 v = part[q * 256 + urow * 32 + b_r];
                addf2(aif, v.x); addf2(ago, v.y);
            }
            float zi, zf, zg, zo;
            unpack2(aif, zi, zf);
            unpack2(ago, zg, zo);
            zi += x_i; zf += x_f; zg += x_g; zo += x_o;

            float iv = 1.f / (1.f + expf(-zi));
            float fv = 1.f / (1.f + expf(-zf));
            float gv = tanhf(zg);
            float ov = 1.f / (1.f + expf(-zo));
            c_reg = fv * c_reg + iv * gv;
            float hv = ov * tanhf(c_reg);

            Hout[((size_t)b_r * T_ + t) * H_ + u_r] = hv;
            g_hT[t & 1][u_r * 32 + b_r] = hv;
        }

        __threadfence();
        grid_sync(&gen_local);
    }
}

// ---------------------------------------------------------------------------
extern "C" void kernel_launch(void* const* d_in, const int* in_sizes, int n_in,
                              void* d_out, int out_size)
{
    const float* obs = (const float*)d_in[0];
    const float* W1x = (const float*)d_in[1];
    const float* W1h = (const float*)d_in[2];
    const float* b1  = (const float*)d_in[3];
    const float* W2x = (const float*)d_in[4];
    const float* W2h = (const float*)d_in[5];
    const float* b2  = (const float*)d_in[6];
    const float* Wm  = (const float*)d_in[7];
    const float* bm  = (const float*)d_in[8];
    const float* Wc  = (const float*)d_in[9];
    const float* bc  = (const float*)d_in[10];

    float *XZ, *H1, *H2;
    cudaGetSymbolAddress((void**)&XZ, g_XZ);
    cudaGetSymbolAddress((void**)&H1, g_H1);
    cudaGetSymbolAddress((void**)&H2, g_H2);

    float* out = (float*)d_out;
    size_t half = (size_t)out_size / 2;   // mean | cov

    const int DSMEM = H_ * 8 * 4 * (int)sizeof(float)       // W slice   128KB
                    + 2 * 256 * 32 * (int)sizeof(float);    // h dbl buf  64KB (aliased by partials)
    cudaFuncSetAttribute(lstm_layer_persist,
                         cudaFuncAttributeMaxDynamicSharedMemorySize, DSMEM);

    // XZ1 = obs @ W1x + b1
    gemm_bias<0><<<dim3(FH_ / 128, BT_ / 128), 256>>>(obs, W1x, b1, XZ, BT_, FH_, DIN_, FH_);

    // Layer 1 recurrence (persistent)
    lstm_layer_persist<<<NBLK_, NTH_, DSMEM>>>(W1h, XZ, H1);

    // XZ2 = H1 @ W2x + b2  (reuse XZ buffer)
    gemm_bias<0><<<dim3(FH_ / 128, BT_ / 128), 256>>>(H1, W2x, b2, XZ, BT_, FH_, H_, FH_);

    // Layer 2 recurrence
    lstm_layer_persist<<<NBLK_, NTH_, DSMEM>>>(W2h, XZ, H2);

    // Heads: mean = H2@Wm + bm ; cov = softplus(H2@Wc + bc)
    gemm_bias<0><<<dim3(DOUT_ / 128, BT_ / 128), 256>>>(H2, Wm, bm, out,        BT_, DOUT_, H_, DOUT_);
    gemm_bias<1><<<dim3(DOUT_ / 128, BT_ / 128), 256>>>(H2, Wc, bc, out + half, BT_, DOUT_, H_, DOUT_);
}

// round 9
// speedup vs baseline: 2.4076x; 1.3954x over previous
#include <cuda_runtime.h>
#include <cuda_bf16.h>
#include <math.h>
#include <stdint.h>

#define B_    32
#define T_    1024
#define H_    1024
#define FH_   4096
#define DIN_  256
#define DOUT_ 512
#define BT_   (B_*T_)
#define NBLK_ 128
#define NTH_R 256

typedef unsigned long long ull;

// -------- scratch (static device globals; no allocation anywhere) ----------
__device__ float g_XZ[(size_t)BT_*FH_];    // 512 MB
__device__ float g_H1[(size_t)BT_*H_];     // 128 MB
__device__ float g_H2[(size_t)BT_*H_];     // 128 MB
__device__ __nv_bfloat16 g_hA[2][64*1024]; // A mirror: rows 0-31 h_hi, 32-63 h_lo

// grid barrier (generation-relative => safe across graph replays)
__device__ unsigned          g_bar_count = 0;
__device__ volatile unsigned g_bar_gen   = 0;

__device__ __forceinline__ void grid_sync(unsigned* gen_local)
{
    __syncthreads();
    if (threadIdx.x == 0) {
        unsigned my = *gen_local;
        __threadfence();
        unsigned arr = atomicAdd(&g_bar_count, 1u);
        if (arr == NBLK_ - 1) {
            g_bar_count = 0;
            __threadfence();
            g_bar_gen = my + 1;
        } else {
            while (g_bar_gen == my) { }
        }
        *gen_local = my + 1;
    }
    __syncthreads();
}

// ---- packed f32x2 helpers (GEMM path) -------------------------------------
__device__ __forceinline__ ull splat2(float x)
{
    ull r; unsigned xi = __float_as_uint(x);
    asm("mov.b64 %0, {%1, %1};" : "=l"(r) : "r"(xi));
    return r;
}
__device__ __forceinline__ void ffma2(ull& d, ull a, ull b)
{
    asm("fma.rn.f32x2 %0, %1, %2, %0;" : "+l"(d) : "l"(a), "l"(b));
}
__device__ __forceinline__ void unpack2(ull v, float& lo, float& hi)
{
    unsigned a, b;
    asm("mov.b64 {%0, %1}, %2;" : "=r"(a), "=r"(b) : "l"(v));
    lo = __uint_as_float(a); hi = __uint_as_float(b);
}

// ---- cp.async helpers -----------------------------------------------------
__device__ __forceinline__ void cp_async16(void* sptr, const void* gptr)
{
    unsigned sa = (unsigned)__cvta_generic_to_shared(sptr);
    asm volatile("cp.async.cg.shared.global [%0], [%1], 16;" :: "r"(sa), "l"(gptr));
}
__device__ __forceinline__ void cp_commit()
{
    asm volatile("cp.async.commit_group;" ::: "memory");
}
template<int N> __device__ __forceinline__ void cp_wait()
{
    asm volatile("cp.async.wait_group %0;" :: "n"(N) : "memory");
}

// ---- warp-MMA helpers (base-target instructions; compile for sm_103) ------
__device__ __forceinline__ uint32_t smem_u32(const void* p)
{
    uint32_t a;
    asm("{ .reg .u64 t; cvta.to.shared.u64 t, %1; cvt.u32.u64 %0, t; }" : "=r"(a) : "l"(p));
    return a;
}
__device__ __forceinline__ void ldsm_x4(uint32_t& r0, uint32_t& r1, uint32_t& r2, uint32_t& r3,
                                        uint32_t addr)
{
    asm volatile("ldmatrix.sync.aligned.m8n8.x4.shared.b16 {%0,%1,%2,%3}, [%4];"
                 : "=r"(r0), "=r"(r1), "=r"(r2), "=r"(r3) : "r"(addr));
}
__device__ __forceinline__ void ldsm_x4t(uint32_t& r0, uint32_t& r1, uint32_t& r2, uint32_t& r3,
                                         uint32_t addr)
{
    asm volatile("ldmatrix.sync.aligned.m8n8.x4.trans.shared.b16 {%0,%1,%2,%3}, [%4];"
                 : "=r"(r0), "=r"(r1), "=r"(r2), "=r"(r3) : "r"(addr));
}
__device__ __forceinline__ void mma16816(float* d,
                                         uint32_t a0, uint32_t a1, uint32_t a2, uint32_t a3,
                                         uint32_t b0, uint32_t b1)
{
    asm volatile("mma.sync.aligned.m16n8k16.row.col.f32.bf16.bf16.f32 "
                 "{%0,%1,%2,%3}, {%4,%5,%6,%7}, {%8,%9}, {%0,%1,%2,%3};"
                 : "+f"(d[0]), "+f"(d[1]), "+f"(d[2]), "+f"(d[3])
                 : "r"(a0), "r"(a1), "r"(a2), "r"(a3), "r"(b0), "r"(b1));
}

// swizzles: conflict-free ldmatrix address groups
// W [1024 k][4 nb units of 16B]: unit' = nb ^ ((k>>1)&3)
#define SW_B(k, nb) ((uint32_t)(k) * 64u + (uint32_t)((((nb) ^ (((k) >> 1) & 3))) * 16))
// A chunk [64 m][32 units of 16B]: unit' = unit ^ (m&7)
#define SW_A(m, unit) ((uint32_t)(m) * 512u + (uint32_t)((((unit) ^ ((m) & 7))) * 16))

// ---- recurrence smem layout (bytes) ---------------------------------------
#define SO_WHI   0
#define SO_WLO   65536
#define SO_A     131072          // 2 x 32768
#define SO_XZ    196608          // [32][33] f32 = 4224
#define SO_Z     200832          // [64][33] f32 = 8448
#define SMEM_R   209280

// ---------------------------------------------------------------------------
// fp32 GEMM + bias (+ optional softplus), FFMA2 inner kernel (unchanged).
// ---------------------------------------------------------------------------
template<int EPI>
__global__ __launch_bounds__(256, 2)
void gemm_bias(const float* __restrict__ A, const float* __restrict__ Bm,
               const float* __restrict__ bias, float* __restrict__ C,
               int M, int N, int K, int ldc)
{
    __shared__ __align__(16) float As[2][16][132];
    __shared__ __align__(16) float Bs[2][16][128];

    const int tid = threadIdx.x;
    const int tx  = tid & 15;
    const int ty  = tid >> 4;
    const int bm  = blockIdx.y * 128;
    const int bn  = blockIdx.x * 128;
    const int br  = tid >> 5;
    const int bc4 = tid & 31;

    float  a_reg[8];
    float4 b_reg[2];

    #pragma unroll
    for (int p = 0; p < 8; p++)
        a_reg[p] = A[(size_t)(bm + ty + p * 16) * K + tx];
    b_reg[0] = *(const float4*)&Bm[(size_t)br       * N + bn + bc4 * 4];
    b_reg[1] = *(const float4*)&Bm[(size_t)(br + 8) * N + bn + bc4 * 4];

    #pragma unroll
    for (int p = 0; p < 8; p++) As[0][tx][ty + p * 16] = a_reg[p];
    *(float4*)&Bs[0][br][bc4 * 4]     = b_reg[0];
    *(float4*)&Bs[0][br + 8][bc4 * 4] = b_reg[1];
    __syncthreads();

    ull acc2[8][4] = {};
    const int nk = K / 16;

    for (int c = 0; c < nk; c++) {
        const int buf = c & 1;

        if (c + 1 < nk) {
            const int k0 = (c + 1) * 16;
            #pragma unroll
            for (int p = 0; p < 8; p++)
                a_reg[p] = A[(size_t)(bm + ty + p * 16) * K + k0 + tx];
            b_reg[0] = *(const float4*)&Bm[(size_t)(k0 + br)     * N + bn + bc4 * 4];
            b_reg[1] = *(const float4*)&Bm[(size_t)(k0 + br + 8) * N + bn + bc4 * 4];
        }

        #pragma unroll
        for (int k = 0; k < 16; k++) {
            float4 a0 = *(const float4*)&As[buf][k][ty * 8];
            float4 a1 = *(const float4*)&As[buf][k][ty * 8 + 4];
            float av[8] = {a0.x, a0.y, a0.z, a0.w, a1.x, a1.y, a1.z, a1.w};
            ull as2[8];
            #pragma unroll
            for (int i = 0; i < 8; i++) as2[i] = splat2(av[i]);

            ulonglong2 bq0 = *(const ulonglong2*)&Bs[buf][k][tx * 8];
            ulonglong2 bq1 = *(const ulonglong2*)&Bs[buf][k][tx * 8 + 4];
            ull bv[4] = {bq0.x, bq0.y, bq1.x, bq1.y};

            #pragma unroll
            for (int i = 0; i < 8; i++)
                #pragma unroll
                for (int jp = 0; jp < 4; jp++)
                    ffma2(acc2[i][jp], as2[i], bv[jp]);
        }
        __syncthreads();

        if (c + 1 < nk) {
            #pragma unroll
            for (int p = 0; p < 8; p++) As[buf ^ 1][tx][ty + p * 16] = a_reg[p];
            *(float4*)&Bs[buf ^ 1][br][bc4 * 4]     = b_reg[0];
            *(float4*)&Bs[buf ^ 1][br + 8][bc4 * 4] = b_reg[1];
            __syncthreads();
        }
    }

    float4 bias0 = *(const float4*)&bias[bn + tx * 8];
    float4 bias1 = *(const float4*)&bias[bn + tx * 8 + 4];
    float bb[8] = {bias0.x, bias0.y, bias0.z, bias0.w, bias1.x, bias1.y, bias1.z, bias1.w};

    #pragma unroll
    for (int i = 0; i < 8; i++) {
        int row = bm + ty * 8 + i;
        float v[8];
        #pragma unroll
        for (int jp = 0; jp < 4; jp++)
            unpack2(acc2[i][jp], v[2 * jp], v[2 * jp + 1]);
        #pragma unroll
        for (int j = 0; j < 8; j++) {
            v[j] += bb[j];
            if (EPI == 1) v[j] = (v[j] > 20.f) ? v[j] : log1pf(expf(v[j]));
        }
        *(float4*)&C[(size_t)row * ldc + bn + tx * 8]     = make_float4(v[0], v[1], v[2], v[3]);
        *(float4*)&C[(size_t)row * ldc + bn + tx * 8 + 4] = make_float4(v[4], v[5], v[6], v[7]);
    }
}

// ---------------------------------------------------------------------------
// Persistent warp-MMA LSTM layer. 128 blocks x 256 threads (8 warps).
// Block owns 8 units (N=32 gate cols). W slice (bf16 hi+lo, swizzled) in SMEM.
// Per step: A=[h_hi;h_lo] (M=64, K=1024) staged in 4 phases; D = A@W_hi+A@W_lo
// via mma.sync.m16n8k16; z[b] = D[b]+D[b+32]+xz; warp 0 does gates (c in regs).
// ---------------------------------------------------------------------------
__global__ __launch_bounds__(NTH_R, 1)
void lstm_layer_mma(const float* __restrict__ Wh,   // [H, 4H]
                    const float* __restrict__ XZ,   // [B*T, 4H] (bias folded)
                    float* __restrict__ Hout)       // [B, T, H]
{
    extern __shared__ __align__(128) char smem[];
    const uint32_t sbase = smem_u32(smem);
    const uint32_t sWHI  = sbase + SO_WHI;
    const uint32_t sWLO  = sbase + SO_WLO;
    const uint32_t sA    = sbase + SO_A;
    float* xzb = (float*)(smem + SO_XZ);   // [32][33]
    float* zb  = (float*)(smem + SO_Z);    // [64][33]

    const int tid  = threadIdx.x;
    const int wid  = tid >> 5;
    const int lane = tid & 31;
    const int u0   = blockIdx.x * 8;

    // ---- one-time: W slice -> bf16 hi/lo, swizzled. col(n) = (n>>3)*H + u0 + (n&7)
    for (int idx = tid; idx < 32 * 1024; idx += NTH_R) {
        int n = idx & 31, k = idx >> 5;
        int gcol = (n >> 3) * H_ + u0 + (n & 7);
        float w = Wh[(size_t)k * FH_ + gcol];
        __nv_bfloat16 hi = __float2bfloat16(w);
        __nv_bfloat16 lo = __float2bfloat16(w - __bfloat162float(hi));
        uint32_t off = SW_B(k, n >> 3) + (uint32_t)(n & 7) * 2;
        *(__nv_bfloat16*)(smem + SO_WHI + off) = hi;
        *(__nv_bfloat16*)(smem + SO_WLO + off) = lo;
    }

    float c_reg[8];
    #pragma unroll
    for (int j = 0; j < 8; j++) c_reg[j] = 0.f;

    unsigned gen_local = 0;
    if (tid == 0) gen_local = g_bar_gen;

    // =========================== t = 0 (h0 = 0) ============================
    {
        #pragma unroll
        for (int i = 0; i < 4; i++) {
            int idx = tid + i * 256;
            int b = idx >> 5, n = idx & 31;
            int gcol = (n >> 3) * H_ + u0 + (n & 7);
            xzb[b * 33 + n] = XZ[(size_t)b * T_ * FH_ + gcol];
        }
        __syncthreads();
        if (wid == 0) {
            __align__(16) __nv_bfloat16 hi8[8], lo8[8];
            #pragma unroll
            for (int j = 0; j < 8; j++) {
                float zi = xzb[lane * 33 + j];
                float zg = xzb[lane * 33 + 16 + j];
                float zo = xzb[lane * 33 + 24 + j];
                float iv = 1.f / (1.f + __expf(-zi));
                float eg = __expf(-2.f * zg); float gv = (1.f - eg) / (1.f + eg);
                float ov = 1.f / (1.f + __expf(-zo));
                float cc = iv * gv;
                c_reg[j] = cc;
                float ec = __expf(-2.f * cc); float tc = (1.f - ec) / (1.f + ec);
                float hv = ov * tc;
                Hout[(size_t)lane * T_ * H_ + u0 + j] = hv;
                hi8[j] = __float2bfloat16(hv);
                lo8[j] = __float2bfloat16(hv - __bfloat162float(hi8[j]));
            }
            *(uint4*)&g_hA[0][(size_t)lane * 1024 + u0]        = *(uint4*)hi8;
            *(uint4*)&g_hA[0][(size_t)(lane + 32) * 1024 + u0] = *(uint4*)lo8;
        }
        __threadfence();
        grid_sync(&gen_local);
    }

    // warp tiling: warp = (m-tile 0-3) x (n-half 0-1)
    const int mt  = wid >> 1;
    const int nh  = wid & 1;                 // n-half: cols nh*16 .. +15
    const int m_loc = mt * 16 + (lane & 7) + ((lane >> 3) & 1) * 8;
    const int krow  = (lane & 7) + ((lane >> 3) & 1) * 8;
    const int nb    = nh * 2 + (lane >> 4);  // 16B n-unit for B ldmatrix
    const int uoff  = lane >> 4;             // extra k-unit for A ldmatrix

    // =========================== main loop =================================
    for (int t = 1; t < T_; t++) {
        const __nv_bfloat16* hA = g_hA[(t - 1) & 1];

        // stage phase 0 -> buf0 (64 rows x 256 k bf16, swizzled)
        #pragma unroll
        for (int i = 0; i < 8; i++) {
            int g = tid + i * 256;
            int r = g >> 5, cc = g & 31;
            cp_async16(smem + SO_A + SW_A(r, cc),
                       (const char*)hA + (size_t)r * 2048 + (size_t)cc * 16);
        }
        cp_commit();

        // prefetch xz gate inputs
        #pragma unroll
        for (int i = 0; i < 4; i++) {
            int idx = tid + i * 256;
            int b = idx >> 5, n = idx & 31;
            int gcol = (n >> 3) * H_ + u0 + (n & 7);
            xzb[b * 33 + n] = XZ[((size_t)b * T_ + t) * FH_ + gcol];
        }

        float d0[4] = {0.f, 0.f, 0.f, 0.f};
        float d1[4] = {0.f, 0.f, 0.f, 0.f};

        #pragma unroll 1
        for (int p = 0; p < 4; p++) {
            cp_wait<0>();
            __syncthreads();

            if (p < 3) {   // prefetch phase p+1 into other buffer
                const char* src = (const char*)hA + (size_t)(p + 1) * 512;
                char* dstb = smem + SO_A + (size_t)((p + 1) & 1) * 32768;
                #pragma unroll
                for (int i = 0; i < 8; i++) {
                    int g = tid + i * 256;
                    int r = g >> 5, cc = g & 31;
                    cp_async16(dstb + SW_A(r, cc),
                               src + (size_t)r * 2048 + (size_t)cc * 16);
                }
                cp_commit();
            }

            const uint32_t abase = sA + (uint32_t)(p & 1) * 32768u;
            #pragma unroll
            for (int ks = 0; ks < 16; ks++) {
                uint32_t a0, a1, a2, a3, b0, b1, b2, b3;
                ldsm_x4(a0, a1, a2, a3, abase + SW_A(m_loc, ks * 2 + uoff));
                int kk = p * 256 + ks * 16 + krow;
                uint32_t boff = SW_B(kk, nb);
                ldsm_x4t(b0, b1, b2, b3, sWHI + boff);
                mma16816(d0, a0, a1, a2, a3, b0, b1);
                mma16816(d1, a0, a1, a2, a3, b2, b3);
                ldsm_x4t(b0, b1, b2, b3, sWLO + boff);
                mma16816(d0, a0, a1, a2, a3, b0, b1);
                mma16816(d1, a0, a1, a2, a3, b2, b3);
            }
        }

        // ---- d-frags -> zb[64][33]
        {
            int row = mt * 16 + (lane >> 2);
            int col = nh * 16 + (lane & 3) * 2;
            zb[row * 33 + col]           = d0[0];
            zb[row * 33 + col + 1]       = d0[1];
            zb[(row + 8) * 33 + col]     = d0[2];
            zb[(row + 8) * 33 + col + 1] = d0[3];
            zb[row * 33 + col + 8]           = d1[0];
            zb[row * 33 + col + 9]           = d1[1];
            zb[(row + 8) * 33 + col + 8]     = d1[2];
            zb[(row + 8) * 33 + col + 9]     = d1[3];
        }
        __syncthreads();

        // ---- gates (warp 0; lane = batch row)
        if (wid == 0) {
            float z[32];
            #pragma unroll
            for (int n = 0; n < 32; n++)
                z[n] = zb[lane * 33 + n] + zb[(lane + 32) * 33 + n] + xzb[lane * 33 + n];

            __align__(16) __nv_bfloat16 hi8[8], lo8[8];
            #pragma unroll
            for (int j = 0; j < 8; j++) {
                float zi = z[j], zf = z[8 + j], zg = z[16 + j], zo = z[24 + j];
                float iv = 1.f / (1.f + __expf(-zi));
                float fv = 1.f / (1.f + __expf(-zf));
                float eg = __expf(-2.f * zg); float gv = (1.f - eg) / (1.f + eg);
                float ov = 1.f / (1.f + __expf(-zo));
                float cc = fv * c_reg[j] + iv * gv;
                c_reg[j] = cc;
                float ec = __expf(-2.f * cc); float tc = (1.f - ec) / (1.f + ec);
                float hv = ov * tc;
                Hout[((size_t)lane * T_ + t) * H_ + u0 + j] = hv;
                hi8[j] = __float2bfloat16(hv);
                lo8[j] = __float2bfloat16(hv - __bfloat162float(hi8[j]));
            }
            *(uint4*)&g_hA[t & 1][(size_t)lane * 1024 + u0]        = *(uint4*)hi8;
            *(uint4*)&g_hA[t & 1][(size_t)(lane + 32) * 1024 + u0] = *(uint4*)lo8;
        }

        __threadfence();
        grid_sync(&gen_local);
    }
}

// ---------------------------------------------------------------------------
extern "C" void kernel_launch(void* const* d_in, const int* in_sizes, int n_in,
                              void* d_out, int out_size)
{
    const float* obs = (const float*)d_in[0];
    const float* W1x = (const float*)d_in[1];
    const float* W1h = (const float*)d_in[2];
    const float* b1  = (const float*)d_in[3];
    const float* W2x = (const float*)d_in[4];
    const float* W2h = (const float*)d_in[5];
    const float* b2  = (const float*)d_in[6];
    const float* Wm  = (const float*)d_in[7];
    const float* bm  = (const float*)d_in[8];
    const float* Wc  = (const float*)d_in[9];
    const float* bc  = (const float*)d_in[10];

    float *XZ, *H1, *H2;
    cudaGetSymbolAddress((void**)&XZ, g_XZ);
    cudaGetSymbolAddress((void**)&H1, g_H1);
    cudaGetSymbolAddress((void**)&H2, g_H2);

    float* out = (float*)d_out;
    size_t half = (size_t)out_size / 2;   // mean | cov

    cudaFuncSetAttribute(lstm_layer_mma,
                         cudaFuncAttributeMaxDynamicSharedMemorySize, SMEM_R);

    // XZ1 = obs @ W1x + b1
    gemm_bias<0><<<dim3(FH_ / 128, BT_ / 128), 256>>>(obs, W1x, b1, XZ, BT_, FH_, DIN_, FH_);

    // Layer 1 recurrence (persistent, warp-MMA)
    lstm_layer_mma<<<NBLK_, NTH_R, SMEM_R>>>(W1h, XZ, H1);

    // XZ2 = H1 @ W2x + b2
    gemm_bias<0><<<dim3(FH_ / 128, BT_ / 128), 256>>>(H1, W2x, b2, XZ, BT_, FH_, H_, FH_);

    // Layer 2 recurrence
    lstm_layer_mma<<<NBLK_, NTH_R, SMEM_R>>>(W2h, XZ, H2);

    // Heads: mean = H2@Wm + bm ; cov = softplus(H2@Wc + bc)
    gemm_bias<0><<<dim3(DOUT_ / 128, BT_ / 128), 256>>>(H2, Wm, bm, out,        BT_, DOUT_, H_, DOUT_);
    gemm_bias<1><<<dim3(DOUT_ / 128, BT_ / 128), 256>>>(H2, Wc, bc, out + half, BT_, DOUT_, H_, DOUT_);
}

// round 10
// speedup vs baseline: 3.5251x; 1.4641x over previous
#include <cuda_runtime.h>
#include <cuda_bf16.h>
#include <math.h>
#include <stdint.h>

#define B_    32
#define T_    1024
#define H_    1024
#define FH_   4096
#define DIN_  256
#define DOUT_ 512
#define BT_   (B_*T_)
#define NBLK_ 128
#define NTH_R 256

// -------- scratch (static device globals; no allocation anywhere) ----------
__device__ float g_XZ[(size_t)BT_*FH_];        // 512 MB, xz for current layer
__device__ __nv_bfloat16 g_Hh[(size_t)BT_*H_]; // layer output hi (reused L1 then L2)
__device__ __nv_bfloat16 g_Hl[(size_t)BT_*H_]; // layer output lo
__device__ __nv_bfloat16 g_hA[2][64*1024];     // step mirror: rows 0-31 h_hi, 32-63 h_lo
// converted operands
__device__ __nv_bfloat16 g_obs_h[(size_t)BT_*DIN_], g_obs_l[(size_t)BT_*DIN_];
__device__ __nv_bfloat16 g_W1x_h[(size_t)DIN_*FH_], g_W1x_l[(size_t)DIN_*FH_];
__device__ __nv_bfloat16 g_W2x_h[(size_t)H_*FH_],   g_W2x_l[(size_t)H_*FH_];
__device__ __nv_bfloat16 g_Wm_h[(size_t)H_*DOUT_],  g_Wm_l[(size_t)H_*DOUT_];
__device__ __nv_bfloat16 g_Wc_h[(size_t)H_*DOUT_],  g_Wc_l[(size_t)H_*DOUT_];

// grid barrier (generation-relative => safe across graph replays)
__device__ unsigned          g_bar_count = 0;
__device__ volatile unsigned g_bar_gen   = 0;

__device__ __forceinline__ void grid_sync(unsigned* gen_local)
{
    __syncthreads();
    if (threadIdx.x == 0) {
        unsigned my = *gen_local;
        __threadfence();
        unsigned arr = atomicAdd(&g_bar_count, 1u);
        if (arr == NBLK_ - 1) {
            g_bar_count = 0;
            __threadfence();
            g_bar_gen = my + 1;
        } else {
            while (g_bar_gen == my) { }
        }
        *gen_local = my + 1;
    }
    __syncthreads();
}

// ---- cp.async helpers -----------------------------------------------------
__device__ __forceinline__ void cp_async16(void* sptr, const void* gptr)
{
    unsigned sa = (unsigned)__cvta_generic_to_shared(sptr);
    asm volatile("cp.async.cg.shared.global [%0], [%1], 16;" :: "r"(sa), "l"(gptr));
}
__device__ __forceinline__ void cp_commit()
{
    asm volatile("cp.async.commit_group;" ::: "memory");
}
template<int N> __device__ __forceinline__ void cp_wait()
{
    asm volatile("cp.async.wait_group %0;" :: "n"(N) : "memory");
}

// ---- warp-MMA helpers -----------------------------------------------------
__device__ __forceinline__ uint32_t smem_u32(const void* p)
{
    uint32_t a;
    asm("{ .reg .u64 t; cvta.to.shared.u64 t, %1; cvt.u32.u64 %0, t; }" : "=r"(a) : "l"(p));
    return a;
}
__device__ __forceinline__ void ldsm_x4(uint32_t& r0, uint32_t& r1, uint32_t& r2, uint32_t& r3,
                                        uint32_t addr)
{
    asm volatile("ldmatrix.sync.aligned.m8n8.x4.shared.b16 {%0,%1,%2,%3}, [%4];"
                 : "=r"(r0), "=r"(r1), "=r"(r2), "=r"(r3) : "r"(addr));
}
__device__ __forceinline__ void ldsm_x4t(uint32_t& r0, uint32_t& r1, uint32_t& r2, uint32_t& r3,
                                         uint32_t addr)
{
    asm volatile("ldmatrix.sync.aligned.m8n8.x4.trans.shared.b16 {%0,%1,%2,%3}, [%4];"
                 : "=r"(r0), "=r"(r1), "=r"(r2), "=r"(r3) : "r"(addr));
}
__device__ __forceinline__ void mma16816(float* d,
                                         uint32_t a0, uint32_t a1, uint32_t a2, uint32_t a3,
                                         uint32_t b0, uint32_t b1)
{
    asm volatile("mma.sync.aligned.m16n8k16.row.col.f32.bf16.bf16.f32 "
                 "{%0,%1,%2,%3}, {%4,%5,%6,%7}, {%8,%9}, {%0,%1,%2,%3};"
                 : "+f"(d[0]), "+f"(d[1]), "+f"(d[2]), "+f"(d[3])
                 : "r"(a0), "r"(a1), "r"(a2), "r"(a3), "r"(b0), "r"(b1));
}

// recurrence swizzles (validated R9)
#define SW_B(k, nb) ((uint32_t)(k) * 64u + (uint32_t)((((nb) ^ (((k) >> 1) & 3))) * 16))
#define SW_A(m, unit) ((uint32_t)(m) * 512u + (uint32_t)((((unit) ^ ((m) & 7))) * 16))

// ---- recurrence smem layout (bytes) ---------------------------------------
#define SO_WHI   0
#define SO_WLO   65536
#define SO_A     131072          // 2 x 32768
#define SO_Z     196608          // [64][33] f32 = 8448
#define SMEM_R   205056

// ---------------------------------------------------------------------------
// fp32 -> bf16 hi/lo conversion (vectorized by 4)
// ---------------------------------------------------------------------------
__global__ void conv_hl(const float* __restrict__ src, __nv_bfloat16* __restrict__ hi,
                        __nv_bfloat16* __restrict__ lo, int n4)
{
    int i = blockIdx.x * blockDim.x + threadIdx.x;
    if (i < n4) {
        float4 v = ((const float4*)src)[i];
        __nv_bfloat16 h[4], l[4];
        float vv[4] = {v.x, v.y, v.z, v.w};
        #pragma unroll
        for (int j = 0; j < 4; j++) {
            h[j] = __float2bfloat16(vv[j]);
            l[j] = __float2bfloat16(vv[j] - __bfloat162float(h[j]));
        }
        ((uint64_t*)hi)[i] = *(uint64_t*)h;
        ((uint64_t*)lo)[i] = *(uint64_t*)l;
    }
}

// ---------------------------------------------------------------------------
// bf16 hi/lo GEMM: C[M,N] = (Ahi+Alo)@(Bhi+Blo) + bias   (3-term, fp32 accum)
// Block tile 128x64, 256 threads (8 warps = 4 mt x 2 nh), BK=16, double-buffered.
// EPI=1 -> softplus epilogue.
// ---------------------------------------------------------------------------
template<int EPI>
__global__ __launch_bounds__(256, 2)
void gemm_bf16_hl(const __nv_bfloat16* __restrict__ Ahi, const __nv_bfloat16* __restrict__ Alo,
                  const __nv_bfloat16* __restrict__ Bhi, const __nv_bfloat16* __restrict__ Blo,
                  const float* __restrict__ bias, float* __restrict__ C,
                  int M, int N, int K, int ldc)
{
    // sA: 2 buf x 2 hl x 128 rows x 48B(pad; 16k bf16=32B) = 24576
    // sB: 2 buf x 2 hl x 16 k x 128B (64 n, XOR-swizzled)   =  8192
    __shared__ __align__(128) char sm[32768];
    const uint32_t sA = smem_u32(sm);
    const uint32_t sB = sA + 24576;

    const int tid  = threadIdx.x;
    const int wid  = tid >> 5;
    const int lane = tid & 31;
    const int mt   = wid >> 1;
    const int nh   = wid & 1;
    const int bm   = blockIdx.y * 128;
    const int bn   = blockIdx.x * 64;

    // loader indices
    const int la_hl = 0;  (void)la_hl;

    // reader addrs (constant across k-iters)
    const int arow0 = mt * 32 + (lane & 7) + ((lane >> 3) & 1) * 8;  // q=0 row
    const int a_u   = lane >> 4;
    const int kr    = lane & 15;
    const int nb0   = nh * 4 + (lane >> 4);       // s=0
    const int nb1   = nh * 4 + 2 + (lane >> 4);   // s=1

    float d[2][2][2][4];
    #pragma unroll
    for (int q = 0; q < 2; q++)
        #pragma unroll
        for (int s = 0; s < 2; s++)
            #pragma unroll
            for (int h8 = 0; h8 < 2; h8++)
                #pragma unroll
                for (int e = 0; e < 4; e++) d[q][s][h8][e] = 0.f;

    const int nk = K / 16;

    // ---- prologue: load k-tile 0 into buf0
    {
        #pragma unroll
        for (int i = 0; i < 2; i++) {
            int idx = tid + i * 256;
            int hl = idx >> 8, rem = idx & 255;
            int r = rem >> 1, u = rem & 1;
            const __nv_bfloat16* src = (hl ? Alo : Ahi) + (size_t)(bm + r) * K + u * 8;
            cp_async16(sm + hl * 6144 + r * 48 + u * 16, src);
        }
        {
            int hl = tid >> 7, rem = tid & 127;
            int kk = rem >> 3, nb = rem & 7;
            const __nv_bfloat16* src = (hl ? Blo : Bhi) + (size_t)kk * N + bn + nb * 8;
            cp_async16(sm + 24576 + hl * 2048 + kk * 128 + ((nb ^ (kk & 7)) * 16), src);
        }
        cp_commit();
    }

    for (int c = 0; c < nk; c++) {
        const int buf = c & 1;
        cp_wait<0>();
        __syncthreads();

        if (c + 1 < nk) {   // prefetch next k-tile into other buffer
            const int k0 = (c + 1) * 16;
            char* base = (char*)sm + ((buf ^ 1) ? 12288 : 0);
            #pragma unroll
            for (int i = 0; i < 2; i++) {
                int idx = tid + i * 256;
                int hl = idx >> 8, rem = idx & 255;
                int r = rem >> 1, u = rem & 1;
                const __nv_bfloat16* src = (hl ? Alo : Ahi) + (size_t)(bm + r) * K + k0 + u * 8;
                cp_async16(base + hl * 6144 + r * 48 + u * 16, src);
            }
            {
                int hl = tid >> 7, rem = tid & 127;
                int kk = rem >> 3, nb = rem & 7;
                const __nv_bfloat16* src = (hl ? Blo : Bhi) + (size_t)(k0 + kk) * N + bn + nb * 8;
                cp_async16((char*)sm + 24576 + ((buf ^ 1) ? 4096 : 0) + hl * 2048
                           + kk * 128 + ((nb ^ (kk & 7)) * 16), src);
            }
            cp_commit();
        }

        const uint32_t aB = sA + buf * 12288;
        const uint32_t bB = sB + buf * 4096;

        uint32_t ah[2][4], al[2][4], bh[2][4], bl[2][4];
        #pragma unroll
        for (int q = 0; q < 2; q++) {
            uint32_t ra = aB + (uint32_t)(arow0 + q * 16) * 48 + a_u * 16;
            ldsm_x4(ah[q][0], ah[q][1], ah[q][2], ah[q][3], ra);
            ldsm_x4(al[q][0], al[q][1], al[q][2], al[q][3], ra + 6144);
        }
        {
            uint32_t r0 = bB + (uint32_t)kr * 128 + ((nb0 ^ (kr & 7)) * 16);
            uint32_t r1 = bB + (uint32_t)kr * 128 + ((nb1 ^ (kr & 7)) * 16);
            ldsm_x4t(bh[0][0], bh[0][1], bh[0][2], bh[0][3], r0);
            ldsm_x4t(bh[1][0], bh[1][1], bh[1][2], bh[1][3], r1);
            ldsm_x4t(bl[0][0], bl[0][1], bl[0][2], bl[0][3], r0 + 2048);
            ldsm_x4t(bl[1][0], bl[1][1], bl[1][2], bl[1][3], r1 + 2048);
        }

        #pragma unroll
        for (int q = 0; q < 2; q++)
            #pragma unroll
            for (int s = 0; s < 2; s++) {
                // Ahi*Bhi + Ahi*Blo + Alo*Bhi  (3-term)
                mma16816(d[q][s][0], ah[q][0], ah[q][1], ah[q][2], ah[q][3], bh[s][0], bh[s][1]);
                mma16816(d[q][s][1], ah[q][0], ah[q][1], ah[q][2], ah[q][3], bh[s][2], bh[s][3]);
                mma16816(d[q][s][0], ah[q][0], ah[q][1], ah[q][2], ah[q][3], bl[s][0], bl[s][1]);
                mma16816(d[q][s][1], ah[q][0], ah[q][1], ah[q][2], ah[q][3], bl[s][2], bl[s][3]);
                mma16816(d[q][s][0], al[q][0], al[q][1], al[q][2], al[q][3], bh[s][0], bh[s][1]);
                mma16816(d[q][s][1], al[q][0], al[q][1], al[q][2], al[q][3], bh[s][2], bh[s][3]);
            }
        __syncthreads();
    }

    // ---- epilogue
    #pragma unroll
    for (int q = 0; q < 2; q++) {
        int row = bm + mt * 32 + q * 16 + (lane >> 2);
        #pragma unroll
        for (int s = 0; s < 2; s++) {
            #pragma unroll
            for (int h8 = 0; h8 < 2; h8++) {
                int col = bn + nh * 32 + s * 16 + h8 * 8 + (lane & 3) * 2;
                float b0 = bias[col], b1 = bias[col + 1];
                float v0 = d[q][s][h8][0] + b0;
                float v1 = d[q][s][h8][1] + b1;
                float v2 = d[q][s][h8][2] + b0;
                float v3 = d[q][s][h8][3] + b1;
                if (EPI == 1) {
                    v0 = (v0 > 20.f) ? v0 : log1pf(expf(v0));
                    v1 = (v1 > 20.f) ? v1 : log1pf(expf(v1));
                    v2 = (v2 > 20.f) ? v2 : log1pf(expf(v2));
                    v3 = (v3 > 20.f) ? v3 : log1pf(expf(v3));
                }
                *(float2*)&C[(size_t)row * ldc + col]       = make_float2(v0, v1);
                *(float2*)&C[(size_t)(row + 8) * ldc + col] = make_float2(v2, v3);
            }
        }
    }
}

// ---------------------------------------------------------------------------
// Persistent warp-MMA LSTM layer (R9 core + all-thread epilogue).
// 128 blocks x 256 threads. Block owns 8 units (N=32 gate cols).
// Epilogue: thread tid = (b = tid>>3, j = tid&7) owns (b, u0+j); c in register.
// Outputs: g_Hh/g_Hl [BT,H] bf16 + g_hA step mirror. No fp32 H array.
// ---------------------------------------------------------------------------
__global__ __launch_bounds__(NTH_R, 1)
void lstm_layer_mma(const float* __restrict__ Wh,   // [H, 4H]
                    const float* __restrict__ XZ)   // [B*T, 4H] (bias folded)
{
    extern __shared__ __align__(128) char smem[];
    const uint32_t sbase = smem_u32(smem);
    const uint32_t sWHI  = sbase + SO_WHI;
    const uint32_t sWLO  = sbase + SO_WLO;
    const uint32_t sA    = sbase + SO_A;
    float* zb = (float*)(smem + SO_Z);    // [64][33]

    const int tid  = threadIdx.x;
    const int wid  = tid >> 5;
    const int lane = tid & 31;
    const int u0   = blockIdx.x * 8;

    // epilogue identity
    const int eb = tid >> 3;      // batch row 0..31
    const int ej = tid & 7;       // unit index 0..7
    const size_t hrow = (size_t)eb * T_;

    // ---- one-time: W slice -> bf16 hi/lo, swizzled. col(n) = (n>>3)*H + u0 + (n&7)
    for (int idx = tid; idx < 32 * 1024; idx += NTH_R) {
        int n = idx & 31, k = idx >> 5;
        int gcol = (n >> 3) * H_ + u0 + (n & 7);
        float w = Wh[(size_t)k * FH_ + gcol];
        __nv_bfloat16 hi = __float2bfloat16(w);
        __nv_bfloat16 lo = __float2bfloat16(w - __bfloat162float(hi));
        uint32_t off = SW_B(k, n >> 3) + (uint32_t)(n & 7) * 2;
        *(__nv_bfloat16*)(smem + SO_WHI + off) = hi;
        *(__nv_bfloat16*)(smem + SO_WLO + off) = lo;
    }

    float c_reg = 0.f;

    unsigned gen_local = 0;
    if (tid == 0) gen_local = g_bar_gen;

    // =========================== t = 0 (h0 = 0) ============================
    {
        const float* xzp = XZ + hrow * FH_ + u0 + ej;
        float zi = __ldg(&xzp[0]);
        float zg = __ldg(&xzp[2 * H_]);
        float zo = __ldg(&xzp[3 * H_]);
        float iv = 1.f / (1.f + __expf(-zi));
        float eg = __expf(-2.f * zg); float gv = (1.f - eg) / (1.f + eg);
        float ov = 1.f / (1.f + __expf(-zo));
        c_reg = iv * gv;
        float ec = __expf(-2.f * c_reg); float tc = (1.f - ec) / (1.f + ec);
        float hv = ov * tc;
        __nv_bfloat16 hi = __float2bfloat16(hv);
        __nv_bfloat16 lo = __float2bfloat16(hv - __bfloat162float(hi));
        g_Hh[hrow * H_ + u0 + ej] = hi;
        g_Hl[hrow * H_ + u0 + ej] = lo;
        g_hA[0][(size_t)eb * 1024 + u0 + ej]        = hi;
        g_hA[0][(size_t)(eb + 32) * 1024 + u0 + ej] = lo;
        __threadfence();
        grid_sync(&gen_local);
    }

    // warp tiling (validated R9): warp = (m-tile 0-3) x (n-half 0-1)
    const int mt  = wid >> 1;
    const int nh  = wid & 1;
    const int m_loc = mt * 16 + (lane & 7) + ((lane >> 3) & 1) * 8;
    const int krow  = (lane & 7) + ((lane >> 3) & 1) * 8;
    const int nb    = nh * 2 + (lane >> 4);
    const int uoff  = lane >> 4;

    // =========================== main loop =================================
    for (int t = 1; t < T_; t++) {
        const __nv_bfloat16* hA = g_hA[(t - 1) & 1];

        // stage phase 0 -> buf0 (64 rows x 256 k bf16, swizzled)
        #pragma unroll
        for (int i = 0; i < 8; i++) {
            int g = tid + i * 256;
            int r = g >> 5, cc = g & 31;
            cp_async16(smem + SO_A + SW_A(r, cc),
                       (const char*)hA + (size_t)r * 2048 + (size_t)cc * 16);
        }
        cp_commit();

        // prefetch xz gate inputs straight into registers
        const float* xzp = XZ + (hrow + t) * FH_ + u0 + ej;
        float x_i = __ldg(&xzp[0]);
        float x_f = __ldg(&xzp[H_]);
        float x_g = __ldg(&xzp[2 * H_]);
        float x_o = __ldg(&xzp[3 * H_]);

        float d0[4] = {0.f, 0.f, 0.f, 0.f};
        float d1[4] = {0.f, 0.f, 0.f, 0.f};

        #pragma unroll 1
        for (int p = 0; p < 4; p++) {
            cp_wait<0>();
            __syncthreads();

            if (p < 3) {   // prefetch phase p+1 into other buffer
                const char* src = (const char*)hA + (size_t)(p + 1) * 512;
                char* dstb = smem + SO_A + (size_t)((p + 1) & 1) * 32768;
                #pragma unroll
                for (int i = 0; i < 8; i++) {
                    int g = tid + i * 256;
                    int r = g >> 5, cc = g & 31;
                    cp_async16(dstb + SW_A(r, cc),
                               src + (size_t)r * 2048 + (size_t)cc * 16);
                }
                cp_commit();
            }

            const uint32_t abase = sA + (uint32_t)(p & 1) * 32768u;
            #pragma unroll
            for (int ks = 0; ks < 16; ks++) {
                uint32_t a0, a1, a2, a3, b0, b1, b2, b3;
                ldsm_x4(a0, a1, a2, a3, abase + SW_A(m_loc, ks * 2 + uoff));
                int kk = p * 256 + ks * 16 + krow;
                uint32_t boff = SW_B(kk, nb);
                ldsm_x4t(b0, b1, b2, b3, sWHI + boff);
                mma16816(d0, a0, a1, a2, a3, b0, b1);
                mma16816(d1, a0, a1, a2, a3, b2, b3);
                ldsm_x4t(b0, b1, b2, b3, sWLO + boff);
                mma16816(d0, a0, a1, a2, a3, b0, b1);
                mma16816(d1, a0, a1, a2, a3, b2, b3);
            }
        }

        // ---- d-frags -> zb[64][33]
        {
            int row = mt * 16 + (lane >> 2);
            int col = nh * 16 + (lane & 3) * 2;
            zb[row * 33 + col]           = d0[0];
            zb[row * 33 + col + 1]       = d0[1];
            zb[(row + 8) * 33 + col]     = d0[2];
            zb[(row + 8) * 33 + col + 1] = d0[3];
            zb[row * 33 + col + 8]           = d1[0];
            zb[row * 33 + col + 9]           = d1[1];
            zb[(row + 8) * 33 + col + 8]     = d1[2];
            zb[(row + 8) * 33 + col + 9]     = d1[3];
        }
        __syncthreads();

        // ---- gates: all 256 threads, one (b, u) each
        {
            float zi = zb[eb * 33 + ej]        + zb[(eb + 32) * 33 + ej]        + x_i;
            float zf = zb[eb * 33 + 8 + ej]    + zb[(eb + 32) * 33 + 8 + ej]    + x_f;
            float zg = zb[eb * 33 + 16 + ej]   + zb[(eb + 32) * 33 + 16 + ej]   + x_g;
            float zo = zb[eb * 33 + 24 + ej]   + zb[(eb + 32) * 33 + 24 + ej]   + x_o;

            float iv = 1.f / (1.f + __expf(-zi));
            float fv = 1.f / (1.f + __expf(-zf));
            float eg = __expf(-2.f * zg); float gv = (1.f - eg) / (1.f + eg);
            float ov = 1.f / (1.f + __expf(-zo));
            c_reg = fv * c_reg + iv * gv;
            float ec = __expf(-2.f * c_reg); float tc = (1.f - ec) / (1.f + ec);
            float hv = ov * tc;

            __nv_bfloat16 hi = __float2bfloat16(hv);
            __nv_bfloat16 lo = __float2bfloat16(hv - __bfloat162float(hi));
            g_Hh[(hrow + t) * H_ + u0 + ej] = hi;
            g_Hl[(hrow + t) * H_ + u0 + ej] = lo;
            g_hA[t & 1][(size_t)eb * 1024 + u0 + ej]        = hi;
            g_hA[t & 1][(size_t)(eb + 32) * 1024 + u0 + ej] = lo;
        }

        __threadfence();
        grid_sync(&gen_local);
    }
}

// ---------------------------------------------------------------------------
extern "C" void kernel_launch(void* const* d_in, const int* in_sizes, int n_in,
                              void* d_out, int out_size)
{
    const float* obs = (const float*)d_in[0];
    const float* W1x = (const float*)d_in[1];
    const float* W1h = (const float*)d_in[2];
    const float* b1  = (const float*)d_in[3];
    const float* W2x = (const float*)d_in[4];
    const float* W2h = (const float*)d_in[5];
    const float* b2  = (const float*)d_in[6];
    const float* Wm  = (const float*)d_in[7];
    const float* bm  = (const float*)d_in[8];
    const float* Wc  = (const float*)d_in[9];
    const float* bc  = (const float*)d_in[10];

    float* XZ;
    __nv_bfloat16 *Hh, *Hl, *obsh, *obsl, *w1xh, *w1xl, *w2xh, *w2xl, *wmh, *wml, *wch, *wcl;
    cudaGetSymbolAddress((void**)&XZ,   g_XZ);
    cudaGetSymbolAddress((void**)&Hh,   g_Hh);
    cudaGetSymbolAddress((void**)&Hl,   g_Hl);
    cudaGetSymbolAddress((void**)&obsh, g_obs_h);
    cudaGetSymbolAddress((void**)&obsl, g_obs_l);
    cudaGetSymbolAddress((void**)&w1xh, g_W1x_h);
    cudaGetSymbolAddress((void**)&w1xl, g_W1x_l);
    cudaGetSymbolAddress((void**)&w2xh, g_W2x_h);
    cudaGetSymbolAddress((void**)&w2xl, g_W2x_l);
    cudaGetSymbolAddress((void**)&wmh,  g_Wm_h);
    cudaGetSymbolAddress((void**)&wml,  g_Wm_l);
    cudaGetSymbolAddress((void**)&wch,  g_Wc_h);
    cudaGetSymbolAddress((void**)&wcl,  g_Wc_l);

    float* out = (float*)d_out;
    size_t half = (size_t)out_size / 2;   // mean | cov

    cudaFuncSetAttribute(lstm_layer_mma,
                         cudaFuncAttributeMaxDynamicSharedMemorySize, SMEM_R);

    // ---- conversions (fp32 -> bf16 hi/lo)
    conv_hl<<<(BT_*DIN_/4 + 255)/256, 256>>>(obs, obsh, obsl, BT_*DIN_/4);
    conv_hl<<<(DIN_*FH_/4 + 255)/256, 256>>>(W1x, w1xh, w1xl, DIN_*FH_/4);
    conv_hl<<<(H_*FH_/4   + 255)/256, 256>>>(W2x, w2xh, w2xl, H_*FH_/4);
    conv_hl<<<(H_*DOUT_/4 + 255)/256, 256>>>(Wm,  wmh,  wml,  H_*DOUT_/4);
    conv_hl<<<(H_*DOUT_/4 + 255)/256, 256>>>(Wc,  wch,  wcl,  H_*DOUT_/4);

    // XZ1 = obs @ W1x + b1
    gemm_bf16_hl<0><<<dim3(FH_/64, BT_/128), 256>>>(obsh, obsl, w1xh, w1xl, b1, XZ,
                                                    BT_, FH_, DIN_, FH_);

    // Layer 1 recurrence -> g_Hh/g_Hl = H1
    lstm_layer_mma<<<NBLK_, NTH_R, SMEM_R>>>(W1h, XZ);

    // XZ2 = H1 @ W2x + b2
    gemm_bf16_hl<0><<<dim3(FH_/64, BT_/128), 256>>>(Hh, Hl, w2xh, w2xl, b2, XZ,
                                                    BT_, FH_, H_, FH_);

    // Layer 2 recurrence -> g_Hh/g_Hl = H2 (overwrites H1 after XZ2 done)
    lstm_layer_mma<<<NBLK_, NTH_R, SMEM_R>>>(W2h, XZ);

    // Heads: mean = H2@Wm + bm ; cov = softplus(H2@Wc + bc)
    gemm_bf16_hl<0><<<dim3(DOUT_/64, BT_/128), 256>>>(Hh, Hl, wmh, wml, bm, out,
                                                      BT_, DOUT_, H_, DOUT_);
    gemm_bf16_hl<1><<<dim3(DOUT_/64, BT_/128), 256>>>(Hh, Hl, wch, wcl, bc, out + half,
                                                      BT_, DOUT_, H_, DOUT_);
}